// round 12
// baseline (speedup 1.0000x reference)
#include <cuda_runtime.h>
#include <cuda_fp16.h>
#include <cstdint>
#include <math.h>

#define B_  16
#define L_  4096
#define D_  512
#define U_  450
#define UP_ 512
#define SCALE_ 0.04419417382415922f     // 1/sqrt(512)
typedef unsigned long long ull;

// ---------------- scratch -------------------------------------------------------
__device__ __half g_xh[(size_t)B_ * L_ * D_];     // X^T pre-split hi (n-major, K=512)
__device__ __half g_xl[(size_t)B_ * L_ * D_];     // X^T lo residual
__device__ __half g_qh[(size_t)B_ * L_ * D_];     // fp16(1024*q) hi
__device__ __half g_ql[(size_t)B_ * L_ * D_];
__device__ __half g_kh[(size_t)B_ * L_ * D_];
__device__ __half g_kl[(size_t)B_ * L_ * D_];
__device__ float g_v[(size_t)B_ * L_ * D_];
__device__ float g_attn[(size_t)B_ * UP_ * L_];
__device__ __half g_ksh[(size_t)B_ * UP_ * D_];   // rows >=450 stay zero
__device__ __half g_ksl[(size_t)B_ * UP_ * D_];
__device__ __half g_qselh[(size_t)B_ * UP_ * D_]; // rows >=450 stay zero
__device__ float g_upd  [(size_t)B_ * UP_ * D_];
__device__ float2 g_mpart[(size_t)B_ * L_ * 4];   // per-(l, n-tile) {max, sum}
__device__ int   g_top[B_ * U_];
__device__ float g_part[B_ * 8 * D_];

// ---------------- helpers -------------------------------------------------------
__device__ __forceinline__ void mma16816(float* c, const uint32_t* a, const uint32_t* b) {
    asm volatile(
        "mma.sync.aligned.m16n8k16.row.col.f32.f16.f16.f32 "
        "{%0,%1,%2,%3}, {%4,%5,%6,%7}, {%8,%9}, {%0,%1,%2,%3};"
        : "+f"(c[0]), "+f"(c[1]), "+f"(c[2]), "+f"(c[3])
        : "r"(a[0]), "r"(a[1]), "r"(a[2]), "r"(a[3]), "r"(b[0]), "r"(b[1]));
}
// fp16 smem XOR swizzle (2B-pair words): rows of 16 uint32 words
__device__ __forceinline__ int hwidx(int row, int w) {
    return (row << 4) | (w ^ ((row << 1) & 14));
}
// 16B-granular swizzle (XOR bits 2,3 only) for the STS128 path
__device__ __forceinline__ int hw4(int row, int w) {
    return (row << 4) | (w ^ ((row << 1) & 12));
}
__device__ __forceinline__ uint32_t packh2(float x, float y) {
    __half2 h = __floats2half2_rn(x, y);
    return *(uint32_t*)&h;
}
__device__ __forceinline__ float2 unpackh2f(uint32_t u) {
    __half2 h = *(__half2*)&u;
    return __half22float2(h);
}

// =================================================================================
// split_x: transpose + fp16-split X = concat(in1,in2).
// =================================================================================
__global__ void __launch_bounds__(256, 1) split_x(
    const float* __restrict__ in1, const float* __restrict__ in2)
{
    __shared__ float t[64][65];
    int b = blockIdx.z;
    int nx = blockIdx.x * 64, ky = blockIdx.y * 64;
    const float* src = (ky < 256)
        ? (in1 + (size_t)b * 256 * 4096 + (size_t)ky * 4096)
        : (in2 + (size_t)b * 256 * 4096 + (size_t)(ky - 256) * 4096);
    int tid = threadIdx.x;
#pragma unroll
    for (int i = 0; i < 4; i++) {
        int task = tid + i * 256;
        int row = task >> 4, q = task & 15;
        float4 v = *(const float4*)(src + (size_t)row * 4096 + nx + q * 4);
        t[row][q * 4 + 0] = v.x; t[row][q * 4 + 1] = v.y;
        t[row][q * 4 + 2] = v.z; t[row][q * 4 + 3] = v.w;
    }
    __syncthreads();
#pragma unroll
    for (int i = 0; i < 2; i++) {
        int task = tid + i * 256;
        int n = task >> 3, oct = task & 7;
        uint32_t hw[4], lw[4];
#pragma unroll
        for (int j = 0; j < 4; j++) {
            float x0 = t[oct * 8 + 2 * j][n];
            float x1 = t[oct * 8 + 2 * j + 1][n];
            hw[j] = packh2(x0, x1);
            float2 f = unpackh2f(hw[j]);
            lw[j] = packh2(x0 - f.x, x1 - f.y);
        }
        size_t off = ((size_t)b * 4096 + nx + n) * 512 + ky + oct * 8;
        *(uint4*)&g_xh[off] = make_uint4(hw[0], hw[1], hw[2], hw[3]);
        *(uint4*)&g_xl[off] = make_uint4(lw[0], lw[1], lw[2], lw[3]);
    }
}

// =================================================================================
// gemm_hx: projection GEMM. A fp32 (M x K) scaled by ascale, split in-kernel;
// B pre-split fp16 (N x K) h/l arrays. R4 loop shape, hw4 swizzle.
//   SPLITOUT=true : write (h,l) fp16 split of 1024*(C+bias) to Ch/Cl (proj q/k)
//   SPLITOUT=false: write fp32 C + bias (proj v)
// =================================================================================
template <int PASSES, bool SPLITOUT>
__global__ void __launch_bounds__(256, 1) gemm_hx(
    const float* __restrict__ A, int lda,
    const __half* __restrict__ Bgh, const __half* __restrict__ Bgl, ull sB,
    float* __restrict__ C, __half* __restrict__ Ch, __half* __restrict__ Cl,
    ull sC, int ldc,
    const float* __restrict__ bias, int K, float ascale, float inv_ascale)
{
    __shared__ __align__(16) uint32_t smh[(PASSES == 3 ? 4 : 2) * 2048];
    uint32_t* Ah = smh;
    uint32_t* Bh = smh + 2048;
    uint32_t* Al = (PASSES == 3) ? smh + 4096 : smh;
    uint32_t* Bl = (PASSES == 3) ? smh + 6144 : smh;

    const int tid = threadIdx.x;
    const int lane = tid & 31, wid = tid >> 5;
    const int g = lane >> 2, tig = lane & 3;
    const int wm = wid & 1, wn = wid >> 1;
    const int z = blockIdx.z;
    Bgh += (size_t)z * sB;
    Bgl += (size_t)z * sB;
    if (!SPLITOUT) C += (size_t)z * sC;
    else { Ch += (size_t)z * sC; Cl += (size_t)z * sC; }
    const int m0 = blockIdx.y * 128, n0 = blockIdx.x * 128;

    float acc[16][4];
#pragma unroll
    for (int i = 0; i < 16; i++)
#pragma unroll
        for (int j = 0; j < 4; j++) acc[i][j] = 0.f;

    float4 pA[4];
    uint4 pBh[2], pBl[2];
    const int NT = K / 32;

    auto loadA = [&](int kt) {
        const float* Ab = A + (size_t)m0 * lda + kt * 32;
#pragma unroll
        for (int it = 0; it < 4; it++) {
            int task = tid + it * 256;
            int r = task >> 3, cq = task & 7;
            pA[it] = *(const float4*)(Ab + (size_t)r * lda + cq * 4);
        }
    };
    auto loadB = [&](int kt) {
#pragma unroll
        for (int it = 0; it < 2; it++) {
            int task = tid + it * 256;
            int r = task >> 2, oct = task & 3;
            size_t off = (size_t)(n0 + r) * K + kt * 32 + oct * 8;
            pBh[it] = *(const uint4*)(Bgh + off);
            if (PASSES == 3) pBl[it] = *(const uint4*)(Bgl + off);
        }
    };
    auto stsAll = [&]() {
#pragma unroll
        for (int it = 0; it < 4; it++) {
            int task = tid + it * 256;
            int r = task >> 3, cq = task & 7;
            float4 v = pA[it];
            v.x *= ascale; v.y *= ascale; v.z *= ascale; v.w *= ascale;
            uint32_t h0 = packh2(v.x, v.y), h1 = packh2(v.z, v.w);
            int w = (2 * cq) ^ ((r << 1) & 12);
            *(uint2*)&Ah[r * 16 + w] = make_uint2(h0, h1);
            if (PASSES == 3) {
                float2 f0 = unpackh2f(h0), f1 = unpackh2f(h1);
                *(uint2*)&Al[r * 16 + w] = make_uint2(
                    packh2(v.x - f0.x, v.y - f0.y),
                    packh2(v.z - f1.x, v.w - f1.y));
            }
        }
#pragma unroll
        for (int it = 0; it < 2; it++) {
            int task = tid + it * 256;
            int r = task >> 2, oct = task & 3;
            int w = (oct * 4) ^ ((r << 1) & 12);
            *(uint4*)&Bh[r * 16 + w] = pBh[it];
            if (PASSES == 3) *(uint4*)&Bl[r * 16 + w] = pBl[it];
        }
    };

    loadA(0); loadB(0);
    for (int kt = 0; kt < NT; kt++) {
        stsAll();
        __syncthreads();
        if (kt + 1 < NT) { loadA(kt + 1); loadB(kt + 1); }
#pragma unroll
        for (int ks = 0; ks < 2; ks++) {
            const int wb = ks * 8;
            uint32_t ah[4][4], bh[4][2], al[4][4], bl[4][2];
#pragma unroll
            for (int mt = 0; mt < 4; mt++) {
                int r0 = wm * 64 + mt * 16 + g, r1 = r0 + 8;
                ah[mt][0] = Ah[hw4(r0, wb + tig)];
                ah[mt][1] = Ah[hw4(r1, wb + tig)];
                ah[mt][2] = Ah[hw4(r0, wb + tig + 4)];
                ah[mt][3] = Ah[hw4(r1, wb + tig + 4)];
                if (PASSES == 3) {
                    al[mt][0] = Al[hw4(r0, wb + tig)];
                    al[mt][1] = Al[hw4(r1, wb + tig)];
                    al[mt][2] = Al[hw4(r0, wb + tig + 4)];
                    al[mt][3] = Al[hw4(r1, wb + tig + 4)];
                }
            }
#pragma unroll
            for (int nt = 0; nt < 4; nt++) {
                int rn = wn * 32 + nt * 8 + g;
                bh[nt][0] = Bh[hw4(rn, wb + tig)];
                bh[nt][1] = Bh[hw4(rn, wb + tig + 4)];
                if (PASSES == 3) {
                    bl[nt][0] = Bl[hw4(rn, wb + tig)];
                    bl[nt][1] = Bl[hw4(rn, wb + tig + 4)];
                }
            }
#pragma unroll
            for (int mt = 0; mt < 4; mt++)
#pragma unroll
                for (int nt = 0; nt < 4; nt++) {
                    mma16816(acc[mt * 4 + nt], ah[mt], bh[nt]);
                    if (PASSES == 3) {
                        mma16816(acc[mt * 4 + nt], ah[mt], bl[nt]);
                        mma16816(acc[mt * 4 + nt], al[mt], bh[nt]);
                    }
                }
        }
        __syncthreads();
    }

#pragma unroll
    for (int mt = 0; mt < 4; mt++) {
        int r0 = m0 + wm * 64 + mt * 16 + g;
        float b0 = bias[r0];
        float b1 = bias[r0 + 8];
#pragma unroll
        for (int nt = 0; nt < 4; nt++) {
            int cc = n0 + wn * 32 + nt * 8 + 2 * tig;
            float* c = acc[mt * 4 + nt];
            if (!SPLITOUT) {
                *(float2*)(C + (size_t)r0 * ldc + cc) =
                    make_float2(c[0] * inv_ascale + b0, c[1] * inv_ascale + b0);
                *(float2*)(C + (size_t)(r0 + 8) * ldc + cc) =
                    make_float2(c[2] * inv_ascale + b1, c[3] * inv_ascale + b1);
            } else {
                float p0 = (c[0] * inv_ascale + b0) * 1024.f;
                float p1 = (c[1] * inv_ascale + b0) * 1024.f;
                float p2 = (c[2] * inv_ascale + b1) * 1024.f;
                float p3 = (c[3] * inv_ascale + b1) * 1024.f;
                __half h0 = __float2half_rn(p0), h1 = __float2half_rn(p1);
                __half h2 = __float2half_rn(p2), h3 = __float2half_rn(p3);
                __half2 hh01 = __halves2half2(h0, h1);
                __half2 hh23 = __halves2half2(h2, h3);
                *(uint32_t*)&Ch[(size_t)r0 * ldc + cc] = *(uint32_t*)&hh01;
                *(uint32_t*)&Ch[(size_t)(r0 + 8) * ldc + cc] = *(uint32_t*)&hh23;
                *(uint32_t*)&Cl[(size_t)r0 * ldc + cc] =
                    packh2(p0 - __half2float(h0), p1 - __half2float(h1));
                *(uint32_t*)&Cl[(size_t)(r0 + 8) * ldc + cc] =
                    packh2(p2 - __half2float(h2), p3 - __half2float(h3));
            }
        }
    }
}

// =================================================================================
// gemm_xx: BOTH operands pre-split fp16 in gmem (rows x K, K-major).
// C[m,n] = inv_scale * sum_k A[m,k]*B[n,k].  R4 loop structure, hw4 swizzle,
// direct LDG128 -> STS128, zero conversion ALU.
//   PASSES=3 : hh+hl+lh;  PASSES=1 : hh only (Agl/Bgl unused)
//   REDUCE   : no C write; per-row {max,sum} over block's 128 cols (<U_) -> mpart
// =================================================================================
template <int PASSES, bool REDUCE>
__global__ void __launch_bounds__(256, 1) gemm_xx(
    const __half* __restrict__ Agh, const __half* __restrict__ Agl, ull sA,
    const __half* __restrict__ Bgh, const __half* __restrict__ Bgl, ull sB,
    float* __restrict__ C, ull sC, int ldc,
    int K, float inv_scale, float2* __restrict__ mpart)
{
    __shared__ __align__(16) uint32_t smh[(PASSES == 3 ? 4 : 2) * 2048];
    uint32_t* Ah = smh;
    uint32_t* Bh = smh + 2048;
    uint32_t* Al = (PASSES == 3) ? smh + 4096 : smh;
    uint32_t* Bl = (PASSES == 3) ? smh + 6144 : smh;

    const int tid = threadIdx.x;
    const int lane = tid & 31, wid = tid >> 5;
    const int g = lane >> 2, tig = lane & 3;
    const int wm = wid & 1, wn = wid >> 1;
    const int z = blockIdx.z;
    Agh += (size_t)z * sA;  Agl += (size_t)z * sA;
    Bgh += (size_t)z * sB;  Bgl += (size_t)z * sB;
    if (!REDUCE) C += (size_t)z * sC;
    const int m0 = blockIdx.y * 128, n0 = blockIdx.x * 128;

    float acc[16][4];
#pragma unroll
    for (int i = 0; i < 16; i++)
#pragma unroll
        for (int j = 0; j < 4; j++) acc[i][j] = 0.f;

    uint4 pAh[2], pAl[2], pBh[2], pBl[2];
    const int NT = K / 32;

    auto loadAll = [&](int kt) {
#pragma unroll
        for (int it = 0; it < 2; it++) {
            int task = tid + it * 256;
            int r = task >> 2, oct = task & 3;
            size_t offA = (size_t)(m0 + r) * K + kt * 32 + oct * 8;
            size_t offB = (size_t)(n0 + r) * K + kt * 32 + oct * 8;
            pAh[it] = *(const uint4*)(Agh + offA);
            pBh[it] = *(const uint4*)(Bgh + offB);
            if (PASSES == 3) {
                pAl[it] = *(const uint4*)(Agl + offA);
                pBl[it] = *(const uint4*)(Bgl + offB);
            }
        }
    };
    auto stsAll = [&]() {
#pragma unroll
        for (int it = 0; it < 2; it++) {
            int task = tid + it * 256;
            int r = task >> 2, oct = task & 3;
            int w = (oct * 4) ^ ((r << 1) & 12);
            *(uint4*)&Ah[r * 16 + w] = pAh[it];
            *(uint4*)&Bh[r * 16 + w] = pBh[it];
            if (PASSES == 3) {
                *(uint4*)&Al[r * 16 + w] = pAl[it];
                *(uint4*)&Bl[r * 16 + w] = pBl[it];
            }
        }
    };

    loadAll(0);
    for (int kt = 0; kt < NT; kt++) {
        stsAll();
        __syncthreads();
        if (kt + 1 < NT) loadAll(kt + 1);
#pragma unroll
        for (int ks = 0; ks < 2; ks++) {
            const int wb = ks * 8;
            uint32_t ah[4][4], bh[4][2], al[4][4], bl[4][2];
#pragma unroll
            for (int mt = 0; mt < 4; mt++) {
                int r0 = wm * 64 + mt * 16 + g, r1 = r0 + 8;
                ah[mt][0] = Ah[hw4(r0, wb + tig)];
                ah[mt][1] = Ah[hw4(r1, wb + tig)];
                ah[mt][2] = Ah[hw4(r0, wb + tig + 4)];
                ah[mt][3] = Ah[hw4(r1, wb + tig + 4)];
                if (PASSES == 3) {
                    al[mt][0] = Al[hw4(r0, wb + tig)];
                    al[mt][1] = Al[hw4(r1, wb + tig)];
                    al[mt][2] = Al[hw4(r0, wb + tig + 4)];
                    al[mt][3] = Al[hw4(r1, wb + tig + 4)];
                }
            }
#pragma unroll
            for (int nt = 0; nt < 4; nt++) {
                int rn = wn * 32 + nt * 8 + g;
                bh[nt][0] = Bh[hw4(rn, wb + tig)];
                bh[nt][1] = Bh[hw4(rn, wb + tig + 4)];
                if (PASSES == 3) {
                    bl[nt][0] = Bl[hw4(rn, wb + tig)];
                    bl[nt][1] = Bl[hw4(rn, wb + tig + 4)];
                }
            }
#pragma unroll
            for (int mt = 0; mt < 4; mt++)
#pragma unroll
                for (int nt = 0; nt < 4; nt++) {
                    mma16816(acc[mt * 4 + nt], ah[mt], bh[nt]);
                    if (PASSES == 3) {
                        mma16816(acc[mt * 4 + nt], ah[mt], bl[nt]);
                        mma16816(acc[mt * 4 + nt], al[mt], bh[nt]);
                    }
                }
        }
        __syncthreads();
    }

    if (!REDUCE) {
#pragma unroll
        for (int mt = 0; mt < 4; mt++) {
            int r0 = m0 + wm * 64 + mt * 16 + g;
#pragma unroll
            for (int nt = 0; nt < 4; nt++) {
                int cc = n0 + wn * 32 + nt * 8 + 2 * tig;
                float* c = acc[mt * 4 + nt];
                *(float2*)(C + (size_t)r0 * ldc + cc) =
                    make_float2(c[0] * inv_scale, c[1] * inv_scale);
                *(float2*)(C + (size_t)(r0 + 8) * ldc + cc) =
                    make_float2(c[2] * inv_scale, c[3] * inv_scale);
            }
        }
    } else {
        float* smax = (float*)smh;            // [128 rows][4 wn]
        float* ssum = smax + 512;
#pragma unroll
        for (int mt = 0; mt < 4; mt++) {
            float m0v = -3.0e38f, s0v = 0.f;
            float m1v = -3.0e38f, s1v = 0.f;
#pragma unroll
            for (int nt = 0; nt < 4; nt++) {
                int cc = n0 + wn * 32 + nt * 8 + 2 * tig;
                float* c = acc[mt * 4 + nt];
#pragma unroll
                for (int e = 0; e < 2; e++) {
                    if (cc + e < U_) {
                        float v0 = c[0 + e] * inv_scale;
                        float v1 = c[2 + e] * inv_scale;
                        m0v = fmaxf(m0v, v0); s0v += v0;
                        m1v = fmaxf(m1v, v1); s1v += v1;
                    }
                }
            }
#pragma unroll
            for (int off = 1; off <= 2; off <<= 1) {
                m0v = fmaxf(m0v, __shfl_xor_sync(0xffffffffu, m0v, off));
                s0v += __shfl_xor_sync(0xffffffffu, s0v, off);
                m1v = fmaxf(m1v, __shfl_xor_sync(0xffffffffu, m1v, off));
                s1v += __shfl_xor_sync(0xffffffffu, s1v, off);
            }
            if (tig == 0) {
                int r0 = wm * 64 + mt * 16 + g;
                smax[r0 * 4 + wn] = m0v;       ssum[r0 * 4 + wn] = s0v;
                smax[(r0 + 8) * 4 + wn] = m1v; ssum[(r0 + 8) * 4 + wn] = s1v;
            }
        }
        __syncthreads();
        if (tid < 128) {
            float mx = smax[tid * 4];
            float sm = ssum[tid * 4];
#pragma unroll
            for (int w = 1; w < 4; w++) {
                mx = fmaxf(mx, smax[tid * 4 + w]);
                sm += ssum[tid * 4 + w];
            }
            mpart[((size_t)z * L_ + m0 + tid) * 4 + blockIdx.x] = make_float2(mx, sm);
        }
    }
}

// =================================================================================
// gemm_h: R7 kernel, used only for upd (TRANSB fp32 path).
// =================================================================================
template <bool TRANSB, int PASSES>
__global__ void __launch_bounds__(256, 1) gemm_h(
    const float* __restrict__ A, ull sA, int lda,
    const float* __restrict__ B1, const float* __restrict__ B2,
    ull sB, int ldb, int splitK,
    float* __restrict__ C, ull sC, int ldc,
    const float* __restrict__ bias, int K, float ascale, float inv_ascale)
{
    __shared__ __align__(16) uint32_t smh[(PASSES == 3 ? 4 : 2) * 2048];
    uint32_t* Ah = smh;
    uint32_t* Bh = smh + 2048;

    const int tid = threadIdx.x;
    const int lane = tid & 31, wid = tid >> 5;
    const int g = lane >> 2, tig = lane & 3;
    const int wm = wid & 1, wn = wid >> 1;
    const int z = blockIdx.z;
    A  += (size_t)z * sA;
    B1 += (size_t)z * sB;
    B2 += (size_t)z * sB;
    C  += (size_t)z * sC;
    const int m0 = blockIdx.y * 128, n0 = blockIdx.x * 128;

    float acc[16][4];
#pragma unroll
    for (int i = 0; i < 16; i++)
#pragma unroll
        for (int j = 0; j < 4; j++) acc[i][j] = 0.f;

    float4 pA[4], pB[4];
    const int NT = K / 32;

    auto loadA = [&](int kt) {
        const float* Ab = A + (size_t)m0 * lda + kt * 32;
#pragma unroll
        for (int it = 0; it < 4; it++) {
            int task = tid + it * 256;
            int r = task >> 3, cq = task & 7;
            pA[it] = *(const float4*)(Ab + (size_t)r * lda + cq * 4);
        }
    };
    auto loadB = [&](int kt) {
        if (!TRANSB) {
            const float* Bb = B1 + (size_t)n0 * ldb + kt * 32;
#pragma unroll
            for (int it = 0; it < 4; it++) {
                int task = tid + it * 256;
                int r = task >> 3, cq = task & 7;
                pB[it] = *(const float4*)(Bb + (size_t)r * ldb + cq * 4);
            }
        } else {
#pragma unroll
            for (int it = 0; it < 4; it++) {
                int task = tid + it * 256;
                int n = task & 127, q = task >> 7;
                int kb = kt * 32 + q * 4;
                float vv[4];
#pragma unroll
                for (int i = 0; i < 4; i++) {
                    int kk = kb + i;
                    const float* row = (kk < splitK)
                        ? (B1 + (size_t)kk * ldb)
                        : (B2 + (size_t)(kk - splitK) * ldb);
                    vv[i] = row[n0 + n];
                }
                pB[it] = make_float4(vv[0], vv[1], vv[2], vv[3]);
            }
        }
    };
    auto stsAll = [&]() {
#pragma unroll
        for (int it = 0; it < 4; it++) {
            int task = tid + it * 256;
            {
                int r = task >> 3, cq = task & 7;
                float4 v = pA[it];
                v.x *= ascale; v.y *= ascale; v.z *= ascale; v.w *= ascale;
                uint32_t h0 = packh2(v.x, v.y), h1 = packh2(v.z, v.w);
                int w = (2 * cq) ^ ((r << 1) & 14);
                *(uint2*)&Ah[r * 16 + w] = make_uint2(h0, h1);
            }
            {
                int r, cq;
                if (!TRANSB) { r = task >> 3; cq = task & 7; }
                else         { r = task & 127; cq = task >> 7; }
                float4 v = pB[it];
                uint32_t h0 = packh2(v.x, v.y), h1 = packh2(v.z, v.w);
                int w = (2 * cq) ^ ((r << 1) & 14);
                *(uint2*)&Bh[r * 16 + w] = make_uint2(h0, h1);
            }
        }
    };

    loadA(0); loadB(0);
    for (int kt = 0; kt < NT; kt++) {
        stsAll();
        __syncthreads();
        if (kt + 1 < NT) { loadA(kt + 1); loadB(kt + 1); }
#pragma unroll
        for (int ks = 0; ks < 2; ks++) {
            const int wb = ks * 8;
            uint32_t ah[4][4], bh[4][2];
#pragma unroll
            for (int mt = 0; mt < 4; mt++) {
                int r0 = wm * 64 + mt * 16 + g, r1 = r0 + 8;
                ah[mt][0] = Ah[hwidx(r0, wb + tig)];
                ah[mt][1] = Ah[hwidx(r1, wb + tig)];
                ah[mt][2] = Ah[hwidx(r0, wb + tig + 4)];
                ah[mt][3] = Ah[hwidx(r1, wb + tig + 4)];
            }
#pragma unroll
            for (int nt = 0; nt < 4; nt++) {
                int rn = wn * 32 + nt * 8 + g;
                bh[nt][0] = Bh[hwidx(rn, wb + tig)];
                bh[nt][1] = Bh[hwidx(rn, wb + tig + 4)];
            }
#pragma unroll
            for (int mt = 0; mt < 4; mt++)
#pragma unroll
                for (int nt = 0; nt < 4; nt++)
                    mma16816(acc[mt * 4 + nt], ah[mt], bh[nt]);
        }
        __syncthreads();
    }

#pragma unroll
    for (int mt = 0; mt < 4; mt++) {
        int r0 = m0 + wm * 64 + mt * 16 + g;
        float b0 = bias ? bias[r0] : 0.f;
        float b1 = bias ? bias[r0 + 8] : 0.f;
#pragma unroll
        for (int nt = 0; nt < 4; nt++) {
            int cc = n0 + wn * 32 + nt * 8 + 2 * tig;
            float* c = acc[mt * 4 + nt];
            *(float2*)(C + (size_t)r0 * ldc + cc) =
                make_float2(c[0] * inv_ascale + b0, c[1] * inv_ascale + b0);
            *(float2*)(C + (size_t)(r0 + 8) * ldc + cc) =
                make_float2(c[2] * inv_ascale + b1, c[3] * inv_ascale + b1);
        }
    }
}

// ---------------- small kernels --------------------------------------------------
__global__ void gather_ksamp(const int* __restrict__ idx)
{
    int b = blockIdx.y, u = blockIdx.x;
    int r = idx[u];
    int t = threadIdx.x;                                      // 128 threads
    if (t < 64) {
        const uint4* s = (const uint4*)(g_kh + ((size_t)b * L_ + r) * D_);
        uint4*       d = (uint4*)(g_ksh + ((size_t)b * UP_ + u) * D_);
        d[t] = s[t];
    } else {
        const uint4* s = (const uint4*)(g_kl + ((size_t)b * L_ + r) * D_);
        uint4*       d = (uint4*)(g_ksl + ((size_t)b * UP_ + u) * D_);
        d[t - 64] = s[t - 64];
    }
}

// top-450 with M computed inline from mpart (tie-break = lower index)
__global__ void topk_kernel()
{
    __shared__ unsigned long long key[4096];
    int b = blockIdx.x;
    for (int i = threadIdx.x; i < 4096; i += 1024) {
        const float2* p = &g_mpart[((size_t)b * L_ + i) * 4];
        float mx = p[0].x, sm = p[0].y;
#pragma unroll
        for (int w = 1; w < 4; w++) { mx = fmaxf(mx, p[w].x); sm += p[w].y; }
        float M = mx - sm * (1.0f / 4096.0f);
        unsigned u = __float_as_uint(M);
        u = (u & 0x80000000u) ? ~u : (u | 0x80000000u);
        key[i] = ((unsigned long long)u << 32) | (unsigned)(4095 - i);
    }
    __syncthreads();
    for (int k = 2; k <= 4096; k <<= 1) {
        for (int j = k >> 1; j > 0; j >>= 1) {
            for (int i = threadIdx.x; i < 4096; i += 1024) {
                int ixj = i ^ j;
                if (ixj > i) {
                    bool up = ((i & k) == 0);
                    unsigned long long a = key[i], c = key[ixj];
                    if ((a > c) == up) { key[i] = c; key[ixj] = a; }
                }
            }
            __syncthreads();
        }
    }
    for (int t = threadIdx.x; t < U_; t += 1024) {
        unsigned long long kk = key[4095 - t];
        g_top[b * U_ + t] = 4095 - (int)(unsigned)(kk & 0xFFFFFFFFu);
    }
}

__global__ void gather_qsel()
{
    int b = blockIdx.y, u = blockIdx.x;
    int r = g_top[b * U_ + u];
    const uint4* s = (const uint4*)(g_qh + ((size_t)b * L_ + r) * D_);
    uint4*       d = (uint4*)(g_qselh + ((size_t)b * UP_ + u) * D_);
    d[threadIdx.x] = s[threadIdx.x];                           // 64 threads
}

__global__ void softmax_kernel()
{
    int b = blockIdx.y, u = blockIdx.x;
    float* row = g_attn + ((size_t)b * UP_ + (size_t)u) * L_;
    int tid = threadIdx.x;
    int lane = tid & 31, wid = tid >> 5;

    float v[16]; float mx = -3.0e38f;
#pragma unroll
    for (int i = 0; i < 16; i++) {
        float t = row[tid + i * 256] * SCALE_;
        v[i] = t; mx = fmaxf(mx, t);
    }
    __shared__ float red[8];
    __shared__ float bcast;
#pragma unroll
    for (int o = 16; o; o >>= 1) mx = fmaxf(mx, __shfl_xor_sync(0xffffffffu, mx, o));
    if (!lane) red[wid] = mx;
    __syncthreads();
    if (!tid) { float m2 = red[0]; for (int w = 1; w < 8; w++) m2 = fmaxf(m2, red[w]); bcast = m2; }
    __syncthreads();
    mx = bcast;

    float sm = 0.f;
#pragma unroll
    for (int i = 0; i < 16; i++) { v[i] = expf(v[i] - mx); sm += v[i]; }
#pragma unroll
    for (int o = 16; o; o >>= 1) sm += __shfl_xor_sync(0xffffffffu, sm, o);
    __syncthreads();
    if (!lane) red[wid] = sm;
    __syncthreads();
    if (!tid) { float s = red[0]; for (int w = 1; w < 8; w++) s += red[w]; bcast = 1.0f / s; }
    __syncthreads();
    float inv = bcast;
#pragma unroll
    for (int i = 0; i < 16; i++) row[tid + i * 256] = v[i] * inv;
}

__global__ void vmean_part()
{
    int b = blockIdx.y, ch = blockIdx.x;
    int d = threadIdx.x;
    const float* base = g_v + (size_t)b * L_ * D_ + (size_t)ch * 512 * D_ + d;
    float s = 0.f;
    for (int l = 0; l < 512; l++) s += base[(size_t)l * D_];
    g_part[(b * 8 + ch) * D_ + d] = s;
}

__global__ void fill_kernel(float* __restrict__ out)
{
    int b = blockIdx.y;
    int l0 = blockIdx.x * 8;
    int d = threadIdx.x;
    float s = 0.f;
#pragma unroll
    for (int c = 0; c < 8; c++) s += g_part[(b * 8 + c) * D_ + d];
    s *= (1.0f / 4096.0f);
    float* o = out + (size_t)b * L_ * D_ + (size_t)l0 * D_ + d;
#pragma unroll
    for (int r = 0; r < 8; r++) o[(size_t)r * D_] = s;
}

__global__ void scatter_kernel(float* __restrict__ out)
{
    int b = blockIdx.y, u = blockIdx.x;
    int r = g_top[b * U_ + u];
    const float4* s = (const float4*)(g_upd + ((size_t)b * UP_ + u) * D_);
    float4*       d = (float4*)(out + ((size_t)b * L_ + r) * D_);
    d[threadIdx.x] = s[threadIdx.x];
}

// =================================================================================
extern "C" void kernel_launch(void* const* d_in, const int* in_sizes, int n_in,
                              void* d_out, int out_size)
{
    const float* in1 = (const float*)d_in[0];
    const float* in2 = (const float*)d_in[1];
    const float* Wq  = (const float*)d_in[2];
    const float* bq  = (const float*)d_in[3];
    const float* Wk  = (const float*)d_in[4];
    const float* bk  = (const float*)d_in[5];
    const float* Wv  = (const float*)d_in[6];
    const float* bv  = (const float*)d_in[7];
    const int*   idx = (const int*)d_in[8];
    float* out = (float*)d_out;

    __half *xhp, *xlp, *qhp, *qlp, *khp, *klp, *kshp, *kslp, *qsp;
    float *vp, *attnp, *upp;
    float2* mpp;
    cudaGetSymbolAddress((void**)&xhp,  g_xh);
    cudaGetSymbolAddress((void**)&xlp,  g_xl);
    cudaGetSymbolAddress((void**)&qhp,  g_qh);
    cudaGetSymbolAddress((void**)&qlp,  g_ql);
    cudaGetSymbolAddress((void**)&khp,  g_kh);
    cudaGetSymbolAddress((void**)&klp,  g_kl);
    cudaGetSymbolAddress((void**)&vp,   g_v);
    cudaGetSymbolAddress((void**)&attnp,g_attn);
    cudaGetSymbolAddress((void**)&kshp, g_ksh);
    cudaGetSymbolAddress((void**)&kslp, g_ksl);
    cudaGetSymbolAddress((void**)&qsp,  g_qselh);
    cudaGetSymbolAddress((void**)&upp,  g_upd);
    cudaGetSymbolAddress((void**)&mpp,  g_mpart);

    const ull sXT  = (ull)L_ * D_;
    const ull sQKV = (ull)L_ * D_;
    const ull sUPD = (ull)UP_ * D_;
    const float AS = 1024.f, IAS = 1.f / 1024.f;
    const float INV20 = 1.f / (1024.f * 1024.f);

    // 0. transpose + pre-split X
    split_x<<<dim3(64, 8, B_), 256>>>(in1, in2);

    // 1. projections: q,k -> pre-split (h,l) of 1024*val; v -> fp32
    gemm_hx<3, true><<<dim3(32, 4, B_), 256>>>(
        Wq, 512, xhp, xlp, sXT, nullptr, qhp, qlp, sQKV, 4096, bq, 512, AS, IAS);
    gemm_hx<3, true><<<dim3(32, 4, B_), 256>>>(
        Wk, 512, xhp, xlp, sXT, nullptr, khp, klp, sQKV, 4096, bk, 512, AS, IAS);
    gemm_hx<1, false><<<dim3(32, 4, B_), 256>>>(
        Wv, 512, xhp, xhp, sXT, vp, nullptr, nullptr, sQKV, 4096, bv, 512, AS, IAS);

    // 2. K_sample gather (fp16 halves)
    gather_ksamp<<<dim3(U_, B_), 128>>>(idx);

    // 3. QKs = q @ ksamp^T : both pre-split, fused {max,sum} reduction
    gemm_xx<3, true><<<dim3(4, 32, B_), 256>>>(
        qhp, qlp, sQKV, kshp, kslp, sUPD,
        nullptr, 0ull, 0, 512, INV20, mpp);

    // 4-5. top-450 (M inline), Q_sel gather (h only)
    topk_kernel<<<B_, 1024>>>();
    gather_qsel<<<dim3(U_, B_), 64>>>();

    // 6. scores = Q_sel @ K^T : both pre-split, 1-pass
    gemm_xx<1, false><<<dim3(32, 4, B_), 256>>>(
        qsp, qsp, sUPD, khp, khp, sQKV,
        attnp, (ull)UP_ * L_, 4096, 512, INV20, nullptr);

    // 7. softmax
    softmax_kernel<<<dim3(U_, B_), 256>>>();

    // 8. upd = attn @ V : fp16 1-pass, V is (K x N) -> TRANSB
    gemm_h<true, 1><<<dim3(4, 4, B_), 256>>>(
        attnp, (ull)UP_ * L_, 4096, vp, vp, sQKV, 512, 4096,
        upp, sUPD, 512, nullptr, 4096, 1.f, 1.f);

    // 9. mean fill + scatter
    vmean_part<<<dim3(8, B_), 512>>>();
    fill_kernel<<<dim3(512, B_), 512>>>(out);
    scatter_kernel<<<dim3(U_, B_), 128>>>(out);
}

// round 14
// speedup vs baseline: 1.0885x; 1.0885x over previous
#include <cuda_runtime.h>
#include <cuda_fp16.h>
#include <cstdint>
#include <math.h>

#define B_  16
#define L_  4096
#define D_  512
#define U_  450
#define UP_ 512
#define SCALE_ 0.04419417382415922f     // 1/sqrt(512)
typedef unsigned long long ull;

// ---------------- scratch -------------------------------------------------------
__device__ __half g_xh[(size_t)B_ * L_ * D_];     // X^T pre-split hi (n-major, K=512)
__device__ __half g_xl[(size_t)B_ * L_ * D_];     // X^T lo residual
__device__ float g_q[(size_t)B_ * L_ * D_];
__device__ float g_k[(size_t)B_ * L_ * D_];
__device__ float g_v[(size_t)B_ * L_ * D_];
__device__ float g_attn[(size_t)B_ * UP_ * L_];
__device__ float g_ksamp[(size_t)B_ * UP_ * D_];  // rows >=450 stay zero
__device__ float g_qsel [(size_t)B_ * UP_ * D_];
__device__ float g_upd  [(size_t)B_ * UP_ * D_];
__device__ float2 g_mpart[(size_t)B_ * L_ * 4];   // per-(l, n-tile) {max, sum}
__device__ int   g_top[B_ * U_];
__device__ float g_part[B_ * 8 * D_];

// ---------------- helpers -------------------------------------------------------
__device__ __forceinline__ void mma16816(float* c, const uint32_t* a, const uint32_t* b) {
    asm volatile(
        "mma.sync.aligned.m16n8k16.row.col.f32.f16.f16.f32 "
        "{%0,%1,%2,%3}, {%4,%5,%6,%7}, {%8,%9}, {%0,%1,%2,%3};"
        : "+f"(c[0]), "+f"(c[1]), "+f"(c[2]), "+f"(c[3])
        : "r"(a[0]), "r"(a[1]), "r"(a[2]), "r"(a[3]), "r"(b[0]), "r"(b[1]));
}
// fp16 smem XOR swizzle (2B-pair words): rows of 16 uint32 words
__device__ __forceinline__ int hwidx(int row, int w) {
    return (row << 4) | (w ^ ((row << 1) & 14));
}
// 16B-granular swizzle (XOR bits 2,3 only) for the STS128 path
__device__ __forceinline__ int hw4(int row, int w) {
    return (row << 4) | (w ^ ((row << 1) & 12));
}
__device__ __forceinline__ uint32_t packh2(float x, float y) {
    __half2 h = __floats2half2_rn(x, y);
    return *(uint32_t*)&h;
}
__device__ __forceinline__ float2 unpackh2f(uint32_t u) {
    __half2 h = *(__half2*)&u;
    return __half22float2(h);
}

// =================================================================================
// split_x: transpose + fp16-split X = concat(in1,in2).
// =================================================================================
__global__ void __launch_bounds__(256, 1) split_x(
    const float* __restrict__ in1, const float* __restrict__ in2)
{
    __shared__ float t[64][65];
    int b = blockIdx.z;
    int nx = blockIdx.x * 64, ky = blockIdx.y * 64;
    const float* src = (ky < 256)
        ? (in1 + (size_t)b * 256 * 4096 + (size_t)ky * 4096)
        : (in2 + (size_t)b * 256 * 4096 + (size_t)(ky - 256) * 4096);
    int tid = threadIdx.x;
#pragma unroll
    for (int i = 0; i < 4; i++) {
        int task = tid + i * 256;
        int row = task >> 4, q = task & 15;
        float4 v = *(const float4*)(src + (size_t)row * 4096 + nx + q * 4);
        t[row][q * 4 + 0] = v.x; t[row][q * 4 + 1] = v.y;
        t[row][q * 4 + 2] = v.z; t[row][q * 4 + 3] = v.w;
    }
    __syncthreads();
#pragma unroll
    for (int i = 0; i < 2; i++) {
        int task = tid + i * 256;
        int n = task >> 3, oct = task & 7;
        uint32_t hw[4], lw[4];
#pragma unroll
        for (int j = 0; j < 4; j++) {
            float x0 = t[oct * 8 + 2 * j][n];
            float x1 = t[oct * 8 + 2 * j + 1][n];
            hw[j] = packh2(x0, x1);
            float2 f = unpackh2f(hw[j]);
            lw[j] = packh2(x0 - f.x, x1 - f.y);
        }
        size_t off = ((size_t)b * 4096 + nx + n) * 512 + ky + oct * 8;
        *(uint4*)&g_xh[off] = make_uint4(hw[0], hw[1], hw[2], hw[3]);
        *(uint4*)&g_xl[off] = make_uint4(lw[0], lw[1], lw[2], lw[3]);
    }
}

// =================================================================================
// gemm_hx: 3-pass projection GEMM (proj q,k). A fp32 scaled+split in-kernel;
// B pre-split fp16 (N x K). R4 loop shape, hw4 swizzle. 128x128 tile.
// =================================================================================
template <int PASSES>
__global__ void __launch_bounds__(256, 1) gemm_hx(
    const float* __restrict__ A, int lda,
    const __half* __restrict__ Bgh, const __half* __restrict__ Bgl, ull sB,
    float* __restrict__ C, ull sC, int ldc,
    const float* __restrict__ bias, int K, float ascale, float inv_ascale)
{
    __shared__ __align__(16) uint32_t smh[(PASSES == 3 ? 4 : 2) * 2048];
    uint32_t* Ah = smh;
    uint32_t* Bh = smh + 2048;
    uint32_t* Al = (PASSES == 3) ? smh + 4096 : smh;
    uint32_t* Bl = (PASSES == 3) ? smh + 6144 : smh;

    const int tid = threadIdx.x;
    const int lane = tid & 31, wid = tid >> 5;
    const int g = lane >> 2, tig = lane & 3;
    const int wm = wid & 1, wn = wid >> 1;
    const int z = blockIdx.z;
    Bgh += (size_t)z * sB;
    Bgl += (size_t)z * sB;
    C   += (size_t)z * sC;
    const int m0 = blockIdx.y * 128, n0 = blockIdx.x * 128;

    float acc[16][4];
#pragma unroll
    for (int i = 0; i < 16; i++)
#pragma unroll
        for (int j = 0; j < 4; j++) acc[i][j] = 0.f;

    float4 pA[4];
    uint4 pBh[2], pBl[2];
    const int NT = K / 32;

    auto loadA = [&](int kt) {
        const float* Ab = A + (size_t)m0 * lda + kt * 32;
#pragma unroll
        for (int it = 0; it < 4; it++) {
            int task = tid + it * 256;
            int r = task >> 3, cq = task & 7;
            pA[it] = *(const float4*)(Ab + (size_t)r * lda + cq * 4);
        }
    };
    auto loadB = [&](int kt) {
#pragma unroll
        for (int it = 0; it < 2; it++) {
            int task = tid + it * 256;
            int r = task >> 2, oct = task & 3;
            size_t off = (size_t)(n0 + r) * K + kt * 32 + oct * 8;
            pBh[it] = *(const uint4*)(Bgh + off);
            if (PASSES == 3) pBl[it] = *(const uint4*)(Bgl + off);
        }
    };
    auto stsAll = [&]() {
#pragma unroll
        for (int it = 0; it < 4; it++) {
            int task = tid + it * 256;
            int r = task >> 3, cq = task & 7;
            float4 v = pA[it];
            v.x *= ascale; v.y *= ascale; v.z *= ascale; v.w *= ascale;
            uint32_t h0 = packh2(v.x, v.y), h1 = packh2(v.z, v.w);
            int w = (2 * cq) ^ ((r << 1) & 12);
            *(uint2*)&Ah[r * 16 + w] = make_uint2(h0, h1);
            if (PASSES == 3) {
                float2 f0 = unpackh2f(h0), f1 = unpackh2f(h1);
                *(uint2*)&Al[r * 16 + w] = make_uint2(
                    packh2(v.x - f0.x, v.y - f0.y),
                    packh2(v.z - f1.x, v.w - f1.y));
            }
        }
#pragma unroll
        for (int it = 0; it < 2; it++) {
            int task = tid + it * 256;
            int r = task >> 2, oct = task & 3;
            int w = (oct * 4) ^ ((r << 1) & 12);
            *(uint4*)&Bh[r * 16 + w] = pBh[it];
            if (PASSES == 3) *(uint4*)&Bl[r * 16 + w] = pBl[it];
        }
    };

    loadA(0); loadB(0);
    for (int kt = 0; kt < NT; kt++) {
        stsAll();
        __syncthreads();
        if (kt + 1 < NT) { loadA(kt + 1); loadB(kt + 1); }
#pragma unroll
        for (int ks = 0; ks < 2; ks++) {
            const int wb = ks * 8;
            uint32_t ah[4][4], bh[4][2], al[4][4], bl[4][2];
#pragma unroll
            for (int mt = 0; mt < 4; mt++) {
                int r0 = wm * 64 + mt * 16 + g, r1 = r0 + 8;
                ah[mt][0] = Ah[hw4(r0, wb + tig)];
                ah[mt][1] = Ah[hw4(r1, wb + tig)];
                ah[mt][2] = Ah[hw4(r0, wb + tig + 4)];
                ah[mt][3] = Ah[hw4(r1, wb + tig + 4)];
                if (PASSES == 3) {
                    al[mt][0] = Al[hw4(r0, wb + tig)];
                    al[mt][1] = Al[hw4(r1, wb + tig)];
                    al[mt][2] = Al[hw4(r0, wb + tig + 4)];
                    al[mt][3] = Al[hw4(r1, wb + tig + 4)];
                }
            }
#pragma unroll
            for (int nt = 0; nt < 4; nt++) {
                int rn = wn * 32 + nt * 8 + g;
                bh[nt][0] = Bh[hw4(rn, wb + tig)];
                bh[nt][1] = Bh[hw4(rn, wb + tig + 4)];
                if (PASSES == 3) {
                    bl[nt][0] = Bl[hw4(rn, wb + tig)];
                    bl[nt][1] = Bl[hw4(rn, wb + tig + 4)];
                }
            }
#pragma unroll
            for (int mt = 0; mt < 4; mt++)
#pragma unroll
                for (int nt = 0; nt < 4; nt++) {
                    mma16816(acc[mt * 4 + nt], ah[mt], bh[nt]);
                    if (PASSES == 3) {
                        mma16816(acc[mt * 4 + nt], ah[mt], bl[nt]);
                        mma16816(acc[mt * 4 + nt], al[mt], bh[nt]);
                    }
                }
        }
        __syncthreads();
    }

#pragma unroll
    for (int mt = 0; mt < 4; mt++) {
        int r0 = m0 + wm * 64 + mt * 16 + g;
        float b0 = bias[r0];
        float b1 = bias[r0 + 8];
#pragma unroll
        for (int nt = 0; nt < 4; nt++) {
            int cc = n0 + wn * 32 + nt * 8 + 2 * tig;
            float* c = acc[mt * 4 + nt];
            *(float2*)(C + (size_t)r0 * ldc + cc) =
                make_float2(c[0] * inv_ascale + b0, c[1] * inv_ascale + b0);
            *(float2*)(C + (size_t)(r0 + 8) * ldc + cc) =
                make_float2(c[2] * inv_ascale + b1, c[3] * inv_ascale + b1);
        }
    }
}

// =================================================================================
// gemm_hx64: 1-pass projection GEMM (proj v), 128x64 tile, 2 CTAs/SM.
// A fp32 (M x K) scaled; B pre-split fp16 h (N x K). Same loop shape.
// =================================================================================
__global__ void __launch_bounds__(256, 2) gemm_hx64(
    const float* __restrict__ A, int lda,
    const __half* __restrict__ Bgh, ull sB,
    float* __restrict__ C, ull sC, int ldc,
    const float* __restrict__ bias, int K, float ascale, float inv_ascale)
{
    __shared__ __align__(16) uint32_t smh[2048 + 1024];
    uint32_t* Ah = smh;
    uint32_t* Bh = smh + 2048;

    const int tid = threadIdx.x;
    const int lane = tid & 31, wid = tid >> 5;
    const int g = lane >> 2, tig = lane & 3;
    const int wm = wid & 1, wn = wid >> 1;
    const int z = blockIdx.z;
    Bgh += (size_t)z * sB;
    C   += (size_t)z * sC;
    const int m0 = blockIdx.y * 128, n0 = blockIdx.x * 64;

    float acc[8][4];
#pragma unroll
    for (int i = 0; i < 8; i++)
#pragma unroll
        for (int j = 0; j < 4; j++) acc[i][j] = 0.f;

    float4 pA[4];
    uint4 pBh;
    const int NT = K / 32;

    auto loadA = [&](int kt) {
        const float* Ab = A + (size_t)m0 * lda + kt * 32;
#pragma unroll
        for (int it = 0; it < 4; it++) {
            int task = tid + it * 256;
            int r = task >> 3, cq = task & 7;
            pA[it] = *(const float4*)(Ab + (size_t)r * lda + cq * 4);
        }
    };
    auto loadB = [&](int kt) {
        int r = tid >> 2, oct = tid & 3;
        pBh = *(const uint4*)(Bgh + (size_t)(n0 + r) * K + kt * 32 + oct * 8);
    };
    auto stsAll = [&]() {
#pragma unroll
        for (int it = 0; it < 4; it++) {
            int task = tid + it * 256;
            int r = task >> 3, cq = task & 7;
            float4 v = pA[it];
            v.x *= ascale; v.y *= ascale; v.z *= ascale; v.w *= ascale;
            int w = (2 * cq) ^ ((r << 1) & 12);
            *(uint2*)&Ah[r * 16 + w] = make_uint2(packh2(v.x, v.y), packh2(v.z, v.w));
        }
        {
            int r = tid >> 2, oct = tid & 3;
            int w = (oct * 4) ^ ((r << 1) & 12);
            *(uint4*)&Bh[r * 16 + w] = pBh;
        }
    };

    loadA(0); loadB(0);
    for (int kt = 0; kt < NT; kt++) {
        stsAll();
        __syncthreads();
        if (kt + 1 < NT) { loadA(kt + 1); loadB(kt + 1); }
#pragma unroll
        for (int ks = 0; ks < 2; ks++) {
            const int wb = ks * 8;
            uint32_t ah[4][4], bh[2][2];
#pragma unroll
            for (int mt = 0; mt < 4; mt++) {
                int r0 = wm * 64 + mt * 16 + g, r1 = r0 + 8;
                ah[mt][0] = Ah[hw4(r0, wb + tig)];
                ah[mt][1] = Ah[hw4(r1, wb + tig)];
                ah[mt][2] = Ah[hw4(r0, wb + tig + 4)];
                ah[mt][3] = Ah[hw4(r1, wb + tig + 4)];
            }
#pragma unroll
            for (int nt = 0; nt < 2; nt++) {
                int rn = wn * 16 + nt * 8 + g;
                bh[nt][0] = Bh[hw4(rn, wb + tig)];
                bh[nt][1] = Bh[hw4(rn, wb + tig + 4)];
            }
#pragma unroll
            for (int mt = 0; mt < 4; mt++)
#pragma unroll
                for (int nt = 0; nt < 2; nt++)
                    mma16816(acc[mt * 2 + nt], ah[mt], bh[nt]);
        }
        __syncthreads();
    }

#pragma unroll
    for (int mt = 0; mt < 4; mt++) {
        int r0 = m0 + wm * 64 + mt * 16 + g;
        float b0 = bias ? bias[r0] : 0.f;
        float b1 = bias ? bias[r0 + 8] : 0.f;
#pragma unroll
        for (int nt = 0; nt < 2; nt++) {
            int cc = n0 + wn * 16 + nt * 8 + 2 * tig;
            float* c = acc[mt * 2 + nt];
            *(float2*)(C + (size_t)r0 * ldc + cc) =
                make_float2(c[0] * inv_ascale + b0, c[1] * inv_ascale + b0);
            *(float2*)(C + (size_t)(r0 + 8) * ldc + cc) =
                make_float2(c[2] * inv_ascale + b1, c[3] * inv_ascale + b1);
        }
    }
}

// =================================================================================
// gemm_h: 3-pass fp32-input GEMM with fused reduction (QKs). R7-proven.
// =================================================================================
template <bool TRANSB, int PASSES, bool REDUCE>
__global__ void __launch_bounds__(256, 1) gemm_h(
    const float* __restrict__ A, ull sA, int lda,
    const float* __restrict__ B1, const float* __restrict__ B2,
    ull sB, int ldb, int splitK,
    float* __restrict__ C, ull sC, int ldc,
    const float* __restrict__ bias, int K, float ascale, float inv_ascale,
    float2* __restrict__ mpart)
{
    __shared__ __align__(16) uint32_t smh[(PASSES == 3 ? 4 : 2) * 2048];
    uint32_t* Ah = smh;
    uint32_t* Bh = smh + 2048;
    uint32_t* Al = (PASSES == 3) ? smh + 4096 : smh;
    uint32_t* Bl = (PASSES == 3) ? smh + 6144 : smh;

    const int tid = threadIdx.x;
    const int lane = tid & 31, wid = tid >> 5;
    const int g = lane >> 2, tig = lane & 3;
    const int wm = wid & 1, wn = wid >> 1;
    const int z = blockIdx.z;
    A  += (size_t)z * sA;
    B1 += (size_t)z * sB;
    B2 += (size_t)z * sB;
    C  += (size_t)z * sC;
    const int m0 = blockIdx.y * 128, n0 = blockIdx.x * 128;

    float acc[16][4];
#pragma unroll
    for (int i = 0; i < 16; i++)
#pragma unroll
        for (int j = 0; j < 4; j++) acc[i][j] = 0.f;

    float4 pA[4], pB[4];
    const int NT = K / 32;

    auto loadA = [&](int kt) {
        const float* Ab = A + (size_t)m0 * lda + kt * 32;
#pragma unroll
        for (int it = 0; it < 4; it++) {
            int task = tid + it * 256;
            int r = task >> 3, cq = task & 7;
            pA[it] = *(const float4*)(Ab + (size_t)r * lda + cq * 4);
        }
    };
    auto loadB = [&](int kt) {
        if (!TRANSB) {
            const float* Bb = B1 + (size_t)n0 * ldb + kt * 32;
#pragma unroll
            for (int it = 0; it < 4; it++) {
                int task = tid + it * 256;
                int r = task >> 3, cq = task & 7;
                pB[it] = *(const float4*)(Bb + (size_t)r * ldb + cq * 4);
            }
        } else {
#pragma unroll
            for (int it = 0; it < 4; it++) {
                int task = tid + it * 256;
                int n = task & 127, q = task >> 7;
                int kb = kt * 32 + q * 4;
                float vv[4];
#pragma unroll
                for (int i = 0; i < 4; i++) {
                    int kk = kb + i;
                    const float* row = (kk < splitK)
                        ? (B1 + (size_t)kk * ldb)
                        : (B2 + (size_t)(kk - splitK) * ldb);
                    vv[i] = row[n0 + n];
                }
                pB[it] = make_float4(vv[0], vv[1], vv[2], vv[3]);
            }
        }
    };
    auto stsAll = [&]() {
#pragma unroll
        for (int it = 0; it < 4; it++) {
            int task = tid + it * 256;
            {   // A (scaled)
                int r = task >> 3, cq = task & 7;
                float4 v = pA[it];
                v.x *= ascale; v.y *= ascale; v.z *= ascale; v.w *= ascale;
                uint32_t h0 = packh2(v.x, v.y), h1 = packh2(v.z, v.w);
                int w = (2 * cq) ^ ((r << 1) & 14);
                *(uint2*)&Ah[r * 16 + w] = make_uint2(h0, h1);
                if (PASSES == 3) {
                    float2 f0 = unpackh2f(h0), f1 = unpackh2f(h1);
                    *(uint2*)&Al[r * 16 + w] = make_uint2(
                        packh2(v.x - f0.x, v.y - f0.y),
                        packh2(v.z - f1.x, v.w - f1.y));
                }
            }
            {   // B
                int r, cq;
                if (!TRANSB) { r = task >> 3; cq = task & 7; }
                else         { r = task & 127; cq = task >> 7; }
                float4 v = pB[it];
                uint32_t h0 = packh2(v.x, v.y), h1 = packh2(v.z, v.w);
                int w = (2 * cq) ^ ((r << 1) & 14);
                *(uint2*)&Bh[r * 16 + w] = make_uint2(h0, h1);
                if (PASSES == 3) {
                    float2 f0 = unpackh2f(h0), f1 = unpackh2f(h1);
                    *(uint2*)&Bl[r * 16 + w] = make_uint2(
                        packh2(v.x - f0.x, v.y - f0.y),
                        packh2(v.z - f1.x, v.w - f1.y));
                }
            }
        }
    };

    loadA(0); loadB(0);
    for (int kt = 0; kt < NT; kt++) {
        stsAll();
        __syncthreads();
        if (kt + 1 < NT) { loadA(kt + 1); loadB(kt + 1); }
#pragma unroll
        for (int ks = 0; ks < 2; ks++) {
            const int wb = ks * 8;
            uint32_t ah[4][4], bh[4][2], al[4][4], bl[4][2];
#pragma unroll
            for (int mt = 0; mt < 4; mt++) {
                int r0 = wm * 64 + mt * 16 + g, r1 = r0 + 8;
                ah[mt][0] = Ah[hwidx(r0, wb + tig)];
                ah[mt][1] = Ah[hwidx(r1, wb + tig)];
                ah[mt][2] = Ah[hwidx(r0, wb + tig + 4)];
                ah[mt][3] = Ah[hwidx(r1, wb + tig + 4)];
                if (PASSES == 3) {
                    al[mt][0] = Al[hwidx(r0, wb + tig)];
                    al[mt][1] = Al[hwidx(r1, wb + tig)];
                    al[mt][2] = Al[hwidx(r0, wb + tig + 4)];
                    al[mt][3] = Al[hwidx(r1, wb + tig + 4)];
                }
            }
#pragma unroll
            for (int nt = 0; nt < 4; nt++) {
                int rn = wn * 32 + nt * 8 + g;
                bh[nt][0] = Bh[hwidx(rn, wb + tig)];
                bh[nt][1] = Bh[hwidx(rn, wb + tig + 4)];
                if (PASSES == 3) {
                    bl[nt][0] = Bl[hwidx(rn, wb + tig)];
                    bl[nt][1] = Bl[hwidx(rn, wb + tig + 4)];
                }
            }
#pragma unroll
            for (int mt = 0; mt < 4; mt++)
#pragma unroll
                for (int nt = 0; nt < 4; nt++) {
                    mma16816(acc[mt * 4 + nt], ah[mt], bh[nt]);
                    if (PASSES == 3) {
                        mma16816(acc[mt * 4 + nt], ah[mt], bl[nt]);
                        mma16816(acc[mt * 4 + nt], al[mt], bh[nt]);
                    }
                }
        }
        __syncthreads();
    }

    if (!REDUCE) {
#pragma unroll
        for (int mt = 0; mt < 4; mt++) {
            int r0 = m0 + wm * 64 + mt * 16 + g;
            float b0 = bias ? bias[r0] : 0.f;
            float b1 = bias ? bias[r0 + 8] : 0.f;
#pragma unroll
            for (int nt = 0; nt < 4; nt++) {
                int cc = n0 + wn * 32 + nt * 8 + 2 * tig;
                float* c = acc[mt * 4 + nt];
                *(float2*)(C + (size_t)r0 * ldc + cc) =
                    make_float2(c[0] * inv_ascale + b0, c[1] * inv_ascale + b0);
                *(float2*)(C + (size_t)(r0 + 8) * ldc + cc) =
                    make_float2(c[2] * inv_ascale + b1, c[3] * inv_ascale + b1);
            }
        }
    } else {
        float* smax = (float*)smh;            // [128 rows][4 wn]
        float* ssum = smax + 512;
#pragma unroll
        for (int mt = 0; mt < 4; mt++) {
            float m0v = -3.0e38f, s0v = 0.f;
            float m1v = -3.0e38f, s1v = 0.f;
#pragma unroll
            for (int nt = 0; nt < 4; nt++) {
                int cc = n0 + wn * 32 + nt * 8 + 2 * tig;
                float* c = acc[mt * 4 + nt];
#pragma unroll
                for (int e = 0; e < 2; e++) {
                    if (cc + e < U_) {
                        float v0 = c[0 + e] * inv_ascale;
                        float v1 = c[2 + e] * inv_ascale;
                        m0v = fmaxf(m0v, v0); s0v += v0;
                        m1v = fmaxf(m1v, v1); s1v += v1;
                    }
                }
            }
#pragma unroll
            for (int off = 1; off <= 2; off <<= 1) {
                m0v = fmaxf(m0v, __shfl_xor_sync(0xffffffffu, m0v, off));
                s0v += __shfl_xor_sync(0xffffffffu, s0v, off);
                m1v = fmaxf(m1v, __shfl_xor_sync(0xffffffffu, m1v, off));
                s1v += __shfl_xor_sync(0xffffffffu, s1v, off);
            }
            if (tig == 0) {
                int r0 = wm * 64 + mt * 16 + g;
                smax[r0 * 4 + wn] = m0v;       ssum[r0 * 4 + wn] = s0v;
                smax[(r0 + 8) * 4 + wn] = m1v; ssum[(r0 + 8) * 4 + wn] = s1v;
            }
        }
        __syncthreads();
        if (tid < 128) {
            float mx = smax[tid * 4];
            float sm = ssum[tid * 4];
#pragma unroll
            for (int w = 1; w < 4; w++) {
                mx = fmaxf(mx, smax[tid * 4 + w]);
                sm += ssum[tid * 4 + w];
            }
            mpart[((size_t)z * L_ + m0 + tid) * 4 + blockIdx.x] = make_float2(mx, sm);
        }
    }
}

// =================================================================================
// gemm_h64: 1-pass fp32-input GEMM, 128x64 tile, 2 CTAs/SM (scores, upd).
// C[m,n] = sum_k A[m,k]*B(n,k).
//   TRANSB=false : B is (N x K) row-major
//   TRANSB=true  : B is (K x N) row-major
// =================================================================================
template <bool TRANSB>
__global__ void __launch_bounds__(256, 2) gemm_h64(
    const float* __restrict__ A, ull sA, int lda,
    const float* __restrict__ B1, ull sB, int ldb,
    float* __restrict__ C, ull sC, int ldc, int K)
{
    __shared__ __align__(16) uint32_t smh[2048 + 1024];
    uint32_t* Ah = smh;
    uint32_t* Bh = smh + 2048;

    const int tid = threadIdx.x;
    const int lane = tid & 31, wid = tid >> 5;
    const int g = lane >> 2, tig = lane & 3;
    const int wm = wid & 1, wn = wid >> 1;
    const int z = blockIdx.z;
    A  += (size_t)z * sA;
    B1 += (size_t)z * sB;
    C  += (size_t)z * sC;
    const int m0 = blockIdx.y * 128, n0 = blockIdx.x * 64;

    float acc[8][4];
#pragma unroll
    for (int i = 0; i < 8; i++)
#pragma unroll
        for (int j = 0; j < 4; j++) acc[i][j] = 0.f;

    float4 pA[4], pB[2];
    const int NT = K / 32;

    auto loadA = [&](int kt) {
        const float* Ab = A + (size_t)m0 * lda + kt * 32;
#pragma unroll
        for (int it = 0; it < 4; it++) {
            int task = tid + it * 256;
            int r = task >> 3, cq = task & 7;
            pA[it] = *(const float4*)(Ab + (size_t)r * lda + cq * 4);
        }
    };
    auto loadB = [&](int kt) {
        if (!TRANSB) {
            const float* Bb = B1 + (size_t)n0 * ldb + kt * 32;
#pragma unroll
            for (int it = 0; it < 2; it++) {
                int task = tid + it * 256;
                int r = task >> 3, cq = task & 7;
                pB[it] = *(const float4*)(Bb + (size_t)r * ldb + cq * 4);
            }
        } else {
#pragma unroll
            for (int it = 0; it < 2; it++) {
                int task = tid + it * 256;
                int n = task & 63, q = task >> 6;
                int kb = kt * 32 + q * 4;
                float vv[4];
#pragma unroll
                for (int i = 0; i < 4; i++)
                    vv[i] = B1[(size_t)(kb + i) * ldb + n0 + n];
                pB[it] = make_float4(vv[0], vv[1], vv[2], vv[3]);
            }
        }
    };
    auto stsAll = [&]() {
#pragma unroll
        for (int it = 0; it < 4; it++) {
            int task = tid + it * 256;
            int r = task >> 3, cq = task & 7;
            float4 v = pA[it];
            int w = (2 * cq) ^ ((r << 1) & 14);
            *(uint2*)&Ah[r * 16 + w] = make_uint2(packh2(v.x, v.y), packh2(v.z, v.w));
        }
#pragma unroll
        for (int it = 0; it < 2; it++) {
            int task = tid + it * 256;
            int r, cq;
            if (!TRANSB) { r = task >> 3; cq = task & 7; }
            else         { r = task & 63; cq = task >> 6; }
            float4 v = pB[it];
            int w = (2 * cq) ^ ((r << 1) & 14);
            *(uint2*)&Bh[r * 16 + w] = make_uint2(packh2(v.x, v.y), packh2(v.z, v.w));
        }
    };

    loadA(0); loadB(0);
    for (int kt = 0; kt < NT; kt++) {
        stsAll();
        __syncthreads();
        if (kt + 1 < NT) { loadA(kt + 1); loadB(kt + 1); }
#pragma unroll
        for (int ks = 0; ks < 2; ks++) {
            const int wb = ks * 8;
            uint32_t ah[4][4], bh[2][2];
#pragma unroll
            for (int mt = 0; mt < 4; mt++) {
                int r0 = wm * 64 + mt * 16 + g, r1 = r0 + 8;
                ah[mt][0] = Ah[hwidx(r0, wb + tig)];
                ah[mt][1] = Ah[hwidx(r1, wb + tig)];
                ah[mt][2] = Ah[hwidx(r0, wb + tig + 4)];
                ah[mt][3] = Ah[hwidx(r1, wb + tig + 4)];
            }
#pragma unroll
            for (int nt = 0; nt < 2; nt++) {
                int rn = wn * 16 + nt * 8 + g;
                bh[nt][0] = Bh[hwidx(rn, wb + tig)];
                bh[nt][1] = Bh[hwidx(rn, wb + tig + 4)];
            }
#pragma unroll
            for (int mt = 0; mt < 4; mt++)
#pragma unroll
                for (int nt = 0; nt < 2; nt++)
                    mma16816(acc[mt * 2 + nt], ah[mt], bh[nt]);
        }
        __syncthreads();
    }

#pragma unroll
    for (int mt = 0; mt < 4; mt++) {
        int r0 = m0 + wm * 64 + mt * 16 + g;
#pragma unroll
        for (int nt = 0; nt < 2; nt++) {
            int cc = n0 + wn * 16 + nt * 8 + 2 * tig;
            float* c = acc[mt * 2 + nt];
            *(float2*)(C + (size_t)r0 * ldc + cc) = make_float2(c[0], c[1]);
            *(float2*)(C + (size_t)(r0 + 8) * ldc + cc) = make_float2(c[2], c[3]);
        }
    }
}

// ---------------- small kernels --------------------------------------------------
__global__ void gather_ksamp(const int* __restrict__ idx)
{
    int b = blockIdx.y, u = blockIdx.x;
    int r = idx[u];
    const float4* s = (const float4*)(g_k + ((size_t)b * L_ + r) * D_);
    float4*       d = (float4*)(g_ksamp + ((size_t)b * UP_ + u) * D_);
    d[threadIdx.x] = s[threadIdx.x];
}

__global__ void topk_kernel()
{
    __shared__ unsigned long long key[4096];
    int b = blockIdx.x;
    for (int i = threadIdx.x; i < 4096; i += 1024) {
        const float2* p = &g_mpart[((size_t)b * L_ + i) * 4];
        float mx = p[0].x, sm = p[0].y;
#pragma unroll
        for (int w = 1; w < 4; w++) { mx = fmaxf(mx, p[w].x); sm += p[w].y; }
        float M = mx - sm * (1.0f / 4096.0f);
        unsigned u = __float_as_uint(M);
        u = (u & 0x80000000u) ? ~u : (u | 0x80000000u);
        key[i] = ((unsigned long long)u << 32) | (unsigned)(4095 - i);
    }
    __syncthreads();
    for (int k = 2; k <= 4096; k <<= 1) {
        for (int j = k >> 1; j > 0; j >>= 1) {
            for (int i = threadIdx.x; i < 4096; i += 1024) {
                int ixj = i ^ j;
                if (ixj > i) {
                    bool up = ((i & k) == 0);
                    unsigned long long a = key[i], c = key[ixj];
                    if ((a > c) == up) { key[i] = c; key[ixj] = a; }
                }
            }
            __syncthreads();
        }
    }
    for (int t = threadIdx.x; t < U_; t += 1024) {
        unsigned long long kk = key[4095 - t];
        g_top[b * U_ + t] = 4095 - (int)(unsigned)(kk & 0xFFFFFFFFu);
    }
}

__global__ void gather_qsel()
{
    int b = blockIdx.y, u = blockIdx.x;
    int r = g_top[b * U_ + u];
    const float4* s = (const float4*)(g_q + ((size_t)b * L_ + r) * D_);
    float4*       d = (float4*)(g_qsel + ((size_t)b * UP_ + u) * D_);
    d[threadIdx.x] = s[threadIdx.x];
}

__global__ void softmax_kernel()
{
    int b = blockIdx.y, u = blockIdx.x;
    float* row = g_attn + ((size_t)b * UP_ + (size_t)u) * L_;
    int tid = threadIdx.x;
    int lane = tid & 31, wid = tid >> 5;

    float v[16]; float mx = -3.0e38f;
#pragma unroll
    for (int i = 0; i < 16; i++) {
        float t = row[tid + i * 256] * SCALE_;
        v[i] = t; mx = fmaxf(mx, t);
    }
    __shared__ float red[8];
    __shared__ float bcast;
#pragma unroll
    for (int o = 16; o; o >>= 1) mx = fmaxf(mx, __shfl_xor_sync(0xffffffffu, mx, o));
    if (!lane) red[wid] = mx;
    __syncthreads();
    if (!tid) { float m2 = red[0]; for (int w = 1; w < 8; w++) m2 = fmaxf(m2, red[w]); bcast = m2; }
    __syncthreads();
    mx = bcast;

    float sm = 0.f;
#pragma unroll
    for (int i = 0; i < 16; i++) { v[i] = expf(v[i] - mx); sm += v[i]; }
#pragma unroll
    for (int o = 16; o; o >>= 1) sm += __shfl_xor_sync(0xffffffffu, sm, o);
    __syncthreads();
    if (!lane) red[wid] = sm;
    __syncthreads();
    if (!tid) { float s = red[0]; for (int w = 1; w < 8; w++) s += red[w]; bcast = 1.0f / s; }
    __syncthreads();
    float inv = bcast;
#pragma unroll
    for (int i = 0; i < 16; i++) row[tid + i * 256] = v[i] * inv;
}

__global__ void vmean_part()
{
    int b = blockIdx.y, ch = blockIdx.x;
    int d = threadIdx.x;
    const float* base = g_v + (size_t)b * L_ * D_ + (size_t)ch * 512 * D_ + d;
    float s = 0.f;
    for (int l = 0; l < 512; l++) s += base[(size_t)l * D_];
    g_part[(b * 8 + ch) * D_ + d] = s;
}

__global__ void fill_kernel(float* __restrict__ out)
{
    int b = blockIdx.y;
    int l0 = blockIdx.x * 8;
    int d = threadIdx.x;
    float s = 0.f;
#pragma unroll
    for (int c = 0; c < 8; c++) s += g_part[(b * 8 + c) * D_ + d];
    s *= (1.0f / 4096.0f);
    float* o = out + (size_t)b * L_ * D_ + (size_t)l0 * D_ + d;
#pragma unroll
    for (int r = 0; r < 8; r++) o[(size_t)r * D_] = s;
}

__global__ void scatter_kernel(float* __restrict__ out)
{
    int b = blockIdx.y, u = blockIdx.x;
    int r = g_top[b * U_ + u];
    const float4* s = (const float4*)(g_upd + ((size_t)b * UP_ + u) * D_);
    float4*       d = (float4*)(out + ((size_t)b * L_ + r) * D_);
    d[threadIdx.x] = s[threadIdx.x];
}

// =================================================================================
extern "C" void kernel_launch(void* const* d_in, const int* in_sizes, int n_in,
                              void* d_out, int out_size)
{
    const float* in1 = (const float*)d_in[0];
    const float* in2 = (const float*)d_in[1];
    const float* Wq  = (const float*)d_in[2];
    const float* bq  = (const float*)d_in[3];
    const float* Wk  = (const float*)d_in[4];
    const float* bk  = (const float*)d_in[5];
    const float* Wv  = (const float*)d_in[6];
    const float* bv  = (const float*)d_in[7];
    const int*   idx = (const int*)d_in[8];
    float* out = (float*)d_out;

    __half *xhp, *xlp;
    float *qp, *kp, *vp, *attnp, *ksp, *qsp, *upp;
    float2* mpp;
    cudaGetSymbolAddress((void**)&xhp,  g_xh);
    cudaGetSymbolAddress((void**)&xlp,  g_xl);
    cudaGetSymbolAddress((void**)&qp,   g_q);
    cudaGetSymbolAddress((void**)&kp,   g_k);
    cudaGetSymbolAddress((void**)&vp,   g_v);
    cudaGetSymbolAddress((void**)&attnp,g_attn);
    cudaGetSymbolAddress((void**)&ksp,  g_ksamp);
    cudaGetSymbolAddress((void**)&qsp,  g_qsel);
    cudaGetSymbolAddress((void**)&upp,  g_upd);
    cudaGetSymbolAddress((void**)&mpp,  g_mpart);

    const ull sXT  = (ull)L_ * D_;
    const ull sQKV = (ull)L_ * D_;
    const float AS = 1024.f, IAS = 1.f / 1024.f;

    // 0. transpose + pre-split X
    split_x<<<dim3(64, 8, B_), 256>>>(in1, in2);

    // 1. projections: q,k 3-pass 128x128; v 1-pass 128x64 @ 2 CTA/SM
    gemm_hx<3><<<dim3(32, 4, B_), 256>>>(
        Wq, 512, xhp, xlp, sXT, qp, sQKV, 4096, bq, 512, AS, IAS);
    gemm_hx<3><<<dim3(32, 4, B_), 256>>>(
        Wk, 512, xhp, xlp, sXT, kp, sQKV, 4096, bk, 512, AS, IAS);
    gemm_hx64<<<dim3(64, 4, B_), 256>>>(
        Wv, 512, xhp, sXT, vp, sQKV, 4096, bv, 512, AS, IAS);

    // 2. K_sample gather
    gather_ksamp<<<dim3(U_, B_), 128>>>(idx);

    // 3. QKs = q @ ksamp^T, fused {max,sum} reduction
    gemm_h<false, 3, true><<<dim3(4, 32, B_), 256>>>(
        qp, sQKV, 512, ksp, ksp, (ull)UP_ * D_, 512, 512,
        nullptr, 0ull, 0, nullptr, 512, AS, IAS, mpp);

    // 4-5. top-450 (M inline), Q_sel gather
    topk_kernel<<<B_, 1024>>>();
    gather_qsel<<<dim3(U_, B_), 128>>>();

    // 6. scores = Q_sel @ K^T : 1-pass 128x64 @ 2 CTA/SM
    gemm_h64<false><<<dim3(64, 4, B_), 256>>>(
        qsp, (ull)UP_ * D_, 512, kp, sQKV, 512,
        attnp, (ull)UP_ * L_, 4096, 512);

    // 7. softmax
    softmax_kernel<<<dim3(U_, B_), 256>>>();

    // 8. upd = attn @ V : 1-pass 128x64 @ 2 CTA/SM, V is (K x N) -> TRANSB
    gemm_h64<true><<<dim3(8, 4, B_), 256>>>(
        attnp, (ull)UP_ * L_, 4096, vp, sQKV, 512,
        upp, (ull)UP_ * D_, 512, 4096);

    // 9. mean fill + scatter
    vmean_part<<<dim3(8, B_), 512>>>();
    fill_kernel<<<dim3(512, B_), 512>>>(out);
    scatter_kernel<<<dim3(U_, B_), 128>>>(out);
}

// round 16
// speedup vs baseline: 1.0935x; 1.0046x over previous
#include <cuda_runtime.h>
#include <cuda_fp16.h>
#include <cstdint>
#include <math.h>

#define B_  16
#define L_  4096
#define D_  512
#define U_  450
#define UP_ 512
#define SCALE_ 0.04419417382415922f     // 1/sqrt(512)
typedef unsigned long long ull;

// ---------------- scratch -------------------------------------------------------
__device__ __half g_xh[(size_t)B_ * L_ * D_];     // X^T pre-split hi (pos-major, K=512)
__device__ __half g_xl[(size_t)B_ * L_ * D_];
__device__ float g_q[(size_t)B_ * L_ * D_];
__device__ float g_k[(size_t)B_ * L_ * D_];
__device__ float g_v[(size_t)B_ * L_ * D_];
__device__ float g_attn[(size_t)B_ * UP_ * L_];
__device__ float g_ksamp[(size_t)B_ * UP_ * D_];  // rows >=450 stay zero forever
__device__ float g_qsel [(size_t)B_ * UP_ * D_];
__device__ float g_upd  [(size_t)B_ * UP_ * D_];
__device__ float2 g_mpart[(size_t)B_ * L_ * 4];
__device__ int   g_top[B_ * U_];
__device__ float g_part[B_ * 8 * D_];

// ---------------- helpers -------------------------------------------------------
__device__ __forceinline__ void mma16816(float* c, const uint32_t* a, const uint32_t* b) {
    asm volatile(
        "mma.sync.aligned.m16n8k16.row.col.f32.f16.f16.f32 "
        "{%0,%1,%2,%3}, {%4,%5,%6,%7}, {%8,%9}, {%0,%1,%2,%3};"
        : "+f"(c[0]), "+f"(c[1]), "+f"(c[2]), "+f"(c[3])
        : "r"(a[0]), "r"(a[1]), "r"(a[2]), "r"(a[3]), "r"(b[0]), "r"(b[1]));
}
__device__ __forceinline__ int hwidx(int row, int w) {
    return (row << 4) | (w ^ ((row << 1) & 14));
}
__device__ __forceinline__ int hw4(int row, int w) {
    return (row << 4) | (w ^ ((row << 1) & 12));
}
__device__ __forceinline__ uint32_t packh2(float x, float y) {
    __half2 h = __floats2half2_rn(x, y);
    return *(uint32_t*)&h;
}
__device__ __forceinline__ float2 unpackh2f(uint32_t u) {
    __half2 h = *(__half2*)&u;
    return __half22float2(h);
}

// =================================================================================
// split_x: transpose + fp16-split X = concat(in1,in2).
// =================================================================================
__global__ void __launch_bounds__(256, 1) split_x(
    const float* __restrict__ in1, const float* __restrict__ in2)
{
    __shared__ float t[64][65];
    int b = blockIdx.z;
    int nx = blockIdx.x * 64, ky = blockIdx.y * 64;
    const float* src = (ky < 256)
        ? (in1 + (size_t)b * 256 * 4096 + (size_t)ky * 4096)
        : (in2 + (size_t)b * 256 * 4096 + (size_t)(ky - 256) * 4096);
    int tid = threadIdx.x;
#pragma unroll
    for (int i = 0; i < 4; i++) {
        int task = tid + i * 256;
        int row = task >> 4, q = task & 15;
        float4 v = *(const float4*)(src + (size_t)row * 4096 + nx + q * 4);
        t[row][q * 4 + 0] = v.x; t[row][q * 4 + 1] = v.y;
        t[row][q * 4 + 2] = v.z; t[row][q * 4 + 3] = v.w;
    }
    __syncthreads();
#pragma unroll
    for (int i = 0; i < 2; i++) {
        int task = tid + i * 256;
        int n = task >> 3, oct = task & 7;
        uint32_t hw[4], lw[4];
#pragma unroll
        for (int j = 0; j < 4; j++) {
            float x0 = t[oct * 8 + 2 * j][n];
            float x1 = t[oct * 8 + 2 * j + 1][n];
            hw[j] = packh2(x0, x1);
            float2 f = unpackh2f(hw[j]);
            lw[j] = packh2(x0 - f.x, x1 - f.y);
        }
        size_t off = ((size_t)b * 4096 + nx + n) * 512 + ky + oct * 8;
        *(uint4*)&g_xh[off] = make_uint4(hw[0], hw[1], hw[2], hw[3]);
        *(uint4*)&g_xl[off] = make_uint4(lw[0], lw[1], lw[2], lw[3]);
    }
}

// =================================================================================
// gemm_hx: projection GEMM. A fp32 (M x K) scaled+split in-kernel;
// B pre-split fp16 (N x K). R4 loop shape, hw4 swizzle. 128x128 tile.
// PASSES=3: hh+hl+lh; PASSES=1: hh only (Bgl unused).
// =================================================================================
template <int PASSES>
__global__ void __launch_bounds__(256, 1) gemm_hx(
    const float* __restrict__ A, int lda,
    const __half* __restrict__ Bgh, const __half* __restrict__ Bgl, ull sB,
    float* __restrict__ C, ull sC, int ldc,
    const float* __restrict__ bias, int K, float ascale, float inv_ascale)
{
    __shared__ __align__(16) uint32_t smh[(PASSES == 3 ? 4 : 2) * 2048];
    uint32_t* Ah = smh;
    uint32_t* Bh = smh + 2048;
    uint32_t* Al = (PASSES == 3) ? smh + 4096 : smh;
    uint32_t* Bl = (PASSES == 3) ? smh + 6144 : smh;

    const int tid = threadIdx.x;
    const int lane = tid & 31, wid = tid >> 5;
    const int g = lane >> 2, tig = lane & 3;
    const int wm = wid & 1, wn = wid >> 1;
    const int z = blockIdx.z;
    Bgh += (size_t)z * sB;
    Bgl += (size_t)z * sB;
    C   += (size_t)z * sC;
    const int m0 = blockIdx.y * 128, n0 = blockIdx.x * 128;

    float acc[16][4];
#pragma unroll
    for (int i = 0; i < 16; i++)
#pragma unroll
        for (int j = 0; j < 4; j++) acc[i][j] = 0.f;

    float4 pA[4];
    uint4 pBh[2], pBl[2];
    const int NT = K / 32;

    auto loadA = [&](int kt) {
        const float* Ab = A + (size_t)m0 * lda + kt * 32;
#pragma unroll
        for (int it = 0; it < 4; it++) {
            int task = tid + it * 256;
            int r = task >> 3, cq = task & 7;
            pA[it] = *(const float4*)(Ab + (size_t)r * lda + cq * 4);
        }
    };
    auto loadB = [&](int kt) {
#pragma unroll
        for (int it = 0; it < 2; it++) {
            int task = tid + it * 256;
            int r = task >> 2, oct = task & 3;
            size_t off = (size_t)(n0 + r) * K + kt * 32 + oct * 8;
            pBh[it] = *(const uint4*)(Bgh + off);
            if (PASSES == 3) pBl[it] = *(const uint4*)(Bgl + off);
        }
    };
    auto stsAll = [&]() {
#pragma unroll
        for (int it = 0; it < 4; it++) {
            int task = tid + it * 256;
            int r = task >> 3, cq = task & 7;
            float4 v = pA[it];
            v.x *= ascale; v.y *= ascale; v.z *= ascale; v.w *= ascale;
            uint32_t h0 = packh2(v.x, v.y), h1 = packh2(v.z, v.w);
            int w = (2 * cq) ^ ((r << 1) & 12);
            *(uint2*)&Ah[r * 16 + w] = make_uint2(h0, h1);
            if (PASSES == 3) {
                float2 f0 = unpackh2f(h0), f1 = unpackh2f(h1);
                *(uint2*)&Al[r * 16 + w] = make_uint2(
                    packh2(v.x - f0.x, v.y - f0.y),
                    packh2(v.z - f1.x, v.w - f1.y));
            }
        }
#pragma unroll
        for (int it = 0; it < 2; it++) {
            int task = tid + it * 256;
            int r = task >> 2, oct = task & 3;
            int w = (oct * 4) ^ ((r << 1) & 12);
            *(uint4*)&Bh[r * 16 + w] = pBh[it];
            if (PASSES == 3) *(uint4*)&Bl[r * 16 + w] = pBl[it];
        }
    };

    loadA(0); loadB(0);
    for (int kt = 0; kt < NT; kt++) {
        stsAll();
        __syncthreads();
        if (kt + 1 < NT) { loadA(kt + 1); loadB(kt + 1); }
#pragma unroll
        for (int ks = 0; ks < 2; ks++) {
            const int wb = ks * 8;
            uint32_t ah[4][4], bh[4][2], al[4][4], bl[4][2];
#pragma unroll
            for (int mt = 0; mt < 4; mt++) {
                int r0 = wm * 64 + mt * 16 + g, r1 = r0 + 8;
                ah[mt][0] = Ah[hw4(r0, wb + tig)];
                ah[mt][1] = Ah[hw4(r1, wb + tig)];
                ah[mt][2] = Ah[hw4(r0, wb + tig + 4)];
                ah[mt][3] = Ah[hw4(r1, wb + tig + 4)];
                if (PASSES == 3) {
                    al[mt][0] = Al[hw4(r0, wb + tig)];
                    al[mt][1] = Al[hw4(r1, wb + tig)];
                    al[mt][2] = Al[hw4(r0, wb + tig + 4)];
                    al[mt][3] = Al[hw4(r1, wb + tig + 4)];
                }
            }
#pragma unroll
            for (int nt = 0; nt < 4; nt++) {
                int rn = wn * 32 + nt * 8 + g;
                bh[nt][0] = Bh[hw4(rn, wb + tig)];
                bh[nt][1] = Bh[hw4(rn, wb + tig + 4)];
                if (PASSES == 3) {
                    bl[nt][0] = Bl[hw4(rn, wb + tig)];
                    bl[nt][1] = Bl[hw4(rn, wb + tig + 4)];
                }
            }
#pragma unroll
            for (int mt = 0; mt < 4; mt++)
#pragma unroll
                for (int nt = 0; nt < 4; nt++) {
                    mma16816(acc[mt * 4 + nt], ah[mt], bh[nt]);
                    if (PASSES == 3) {
                        mma16816(acc[mt * 4 + nt], ah[mt], bl[nt]);
                        mma16816(acc[mt * 4 + nt], al[mt], bh[nt]);
                    }
                }
        }
        __syncthreads();
    }

#pragma unroll
    for (int mt = 0; mt < 4; mt++) {
        int r0 = m0 + wm * 64 + mt * 16 + g;
        float b0 = bias[r0];
        float b1 = bias[r0 + 8];
#pragma unroll
        for (int nt = 0; nt < 4; nt++) {
            int cc = n0 + wn * 32 + nt * 8 + 2 * tig;
            float* c = acc[mt * 4 + nt];
            *(float2*)(C + (size_t)r0 * ldc + cc) =
                make_float2(c[0] * inv_ascale + b0, c[1] * inv_ascale + b0);
            *(float2*)(C + (size_t)(r0 + 8) * ldc + cc) =
                make_float2(c[2] * inv_ascale + b1, c[3] * inv_ascale + b1);
        }
    }
}

// =================================================================================
// ksamp_proj: compute ONLY the 450 sampled k rows at 3-pass precision.
// k row l = projection C[o = l>>3, pos = (l&7)*512 + d], so
// ksamp[u,d] = Wk[o_u,:] . XT[(l_u&7)*512 + d, :]  (+ bk[o_u]).
// Blocks: (n-tile 0..3, group 0..7, batch). Per block: scan idx -> group list,
// then gemm_hx<3>-identical mainloop with A rows = gathered Wk rows,
// B slab = contiguous pre-split XT rows. Bit-identical ksamp values to the
// full 3-pass proj-k path (same scaling, split, and K order).
// =================================================================================
__global__ void __launch_bounds__(256, 1) ksamp_proj(
    const float* __restrict__ Wk, const float* __restrict__ bk,
    const int* __restrict__ idx)
{
    __shared__ __align__(16) uint32_t smh[4 * 2048];
    __shared__ int sidx[450];
    __shared__ int lst[452];
    __shared__ int scnt;
    uint32_t* Ah = smh;
    uint32_t* Bh = smh + 2048;
    uint32_t* Al = smh + 4096;
    uint32_t* Bl = smh + 6144;

    const int tid = threadIdx.x;
    const int lane = tid & 31, wid = tid >> 5;
    const int gq = lane >> 2, tig = lane & 3;
    const int wm = wid & 1, wn = wid >> 1;
    const int grp = blockIdx.y;
    const int b = blockIdx.z;
    const int n0 = blockIdx.x * 128;

    for (int i = tid; i < 450; i += 256) sidx[i] = idx[i];
    __syncthreads();
    if (tid == 0) {
        int c = 0;
        for (int u = 0; u < U_; u++) {
            int l = sidx[u];
            if ((l & 7) == grp) lst[c++] = (u << 16) | (l >> 3);
        }
        scnt = c;
    }
    __syncthreads();
    const int cnt = scnt;

    const __half* Bgh = g_xh + ((size_t)b * L_ + grp * 512 + n0) * 512;
    const __half* Bgl = g_xl + ((size_t)b * L_ + grp * 512 + n0) * 512;
    float* ksO = g_ksamp + (size_t)b * UP_ * D_;

    for (int mb = 0; mb < cnt; mb += 128) {
        float acc[16][4];
#pragma unroll
        for (int i = 0; i < 16; i++)
#pragma unroll
            for (int j = 0; j < 4; j++) acc[i][j] = 0.f;

        float4 pA[4];
        uint4 pBh[2], pBl[2];

        auto loadA = [&](int kt) {
#pragma unroll
            for (int it = 0; it < 4; it++) {
                int task = tid + it * 256;
                int r = task >> 3, cq = task & 7;
                int o = (mb + r < cnt) ? (lst[mb + r] & 0xFFFF) : 0;
                pA[it] = *(const float4*)(Wk + (size_t)o * 512 + kt * 32 + cq * 4);
            }
        };
        auto loadB = [&](int kt) {
#pragma unroll
            for (int it = 0; it < 2; it++) {
                int task = tid + it * 256;
                int r = task >> 2, oct = task & 3;
                size_t off = (size_t)r * 512 + kt * 32 + oct * 8;
                pBh[it] = *(const uint4*)(Bgh + off);
                pBl[it] = *(const uint4*)(Bgl + off);
            }
        };
        auto stsAll = [&]() {
#pragma unroll
            for (int it = 0; it < 4; it++) {
                int task = tid + it * 256;
                int r = task >> 3, cq = task & 7;
                float4 v = pA[it];
                v.x *= 1024.f; v.y *= 1024.f; v.z *= 1024.f; v.w *= 1024.f;
                uint32_t h0 = packh2(v.x, v.y), h1 = packh2(v.z, v.w);
                int w = (2 * cq) ^ ((r << 1) & 12);
                *(uint2*)&Ah[r * 16 + w] = make_uint2(h0, h1);
                float2 f0 = unpackh2f(h0), f1 = unpackh2f(h1);
                *(uint2*)&Al[r * 16 + w] = make_uint2(
                    packh2(v.x - f0.x, v.y - f0.y),
                    packh2(v.z - f1.x, v.w - f1.y));
            }
#pragma unroll
            for (int it = 0; it < 2; it++) {
                int task = tid + it * 256;
                int r = task >> 2, oct = task & 3;
                int w = (oct * 4) ^ ((r << 1) & 12);
                *(uint4*)&Bh[r * 16 + w] = pBh[it];
                *(uint4*)&Bl[r * 16 + w] = pBl[it];
            }
        };

        loadA(0); loadB(0);
        for (int kt = 0; kt < 16; kt++) {
            stsAll();
            __syncthreads();
            if (kt + 1 < 16) { loadA(kt + 1); loadB(kt + 1); }
#pragma unroll
            for (int ks = 0; ks < 2; ks++) {
                const int wb = ks * 8;
                uint32_t ah[4][4], bh[4][2], al[4][4], bl[4][2];
#pragma unroll
                for (int mt = 0; mt < 4; mt++) {
                    int r0 = wm * 64 + mt * 16 + gq, r1 = r0 + 8;
                    ah[mt][0] = Ah[hw4(r0, wb + tig)];
                    ah[mt][1] = Ah[hw4(r1, wb + tig)];
                    ah[mt][2] = Ah[hw4(r0, wb + tig + 4)];
                    ah[mt][3] = Ah[hw4(r1, wb + tig + 4)];
                    al[mt][0] = Al[hw4(r0, wb + tig)];
                    al[mt][1] = Al[hw4(r1, wb + tig)];
                    al[mt][2] = Al[hw4(r0, wb + tig + 4)];
                    al[mt][3] = Al[hw4(r1, wb + tig + 4)];
                }
#pragma unroll
                for (int nt = 0; nt < 4; nt++) {
                    int rn = wn * 32 + nt * 8 + gq;
                    bh[nt][0] = Bh[hw4(rn, wb + tig)];
                    bh[nt][1] = Bh[hw4(rn, wb + tig + 4)];
                    bl[nt][0] = Bl[hw4(rn, wb + tig)];
                    bl[nt][1] = Bl[hw4(rn, wb + tig + 4)];
                }
#pragma unroll
                for (int mt = 0; mt < 4; mt++)
#pragma unroll
                    for (int nt = 0; nt < 4; nt++) {
                        mma16816(acc[mt * 4 + nt], ah[mt], bh[nt]);
                        mma16816(acc[mt * 4 + nt], ah[mt], bl[nt]);
                        mma16816(acc[mt * 4 + nt], al[mt], bh[nt]);
                    }
            }
            __syncthreads();
        }

#pragma unroll
        for (int mt = 0; mt < 4; mt++) {
            int gi0 = mb + wm * 64 + mt * 16 + gq;
            int gi1 = gi0 + 8;
            bool v0 = gi0 < cnt, v1 = gi1 < cnt;
            int e0 = v0 ? lst[gi0] : 0;
            int e1 = v1 ? lst[gi1] : 0;
            float b0 = v0 ? bk[e0 & 0xFFFF] : 0.f;
            float b1 = v1 ? bk[e1 & 0xFFFF] : 0.f;
            float* row0 = ksO + (size_t)(e0 >> 16) * D_;
            float* row1 = ksO + (size_t)(e1 >> 16) * D_;
#pragma unroll
            for (int nt = 0; nt < 4; nt++) {
                int cc = n0 + wn * 32 + nt * 8 + 2 * tig;
                float* c = acc[mt * 4 + nt];
                if (v0) *(float2*)(row0 + cc) =
                    make_float2(c[0] * (1.f / 1024.f) + b0, c[1] * (1.f / 1024.f) + b0);
                if (v1) *(float2*)(row1 + cc) =
                    make_float2(c[2] * (1.f / 1024.f) + b1, c[3] * (1.f / 1024.f) + b1);
            }
        }
        __syncthreads();
    }
}

// =================================================================================
// gemm_h: 3-pass fp32-input GEMM with fused reduction (QKs). R7-proven.
// =================================================================================
template <bool TRANSB, int PASSES, bool REDUCE>
__global__ void __launch_bounds__(256, 1) gemm_h(
    const float* __restrict__ A, ull sA, int lda,
    const float* __restrict__ B1, const float* __restrict__ B2,
    ull sB, int ldb, int splitK,
    float* __restrict__ C, ull sC, int ldc,
    const float* __restrict__ bias, int K, float ascale, float inv_ascale,
    float2* __restrict__ mpart)
{
    __shared__ __align__(16) uint32_t smh[(PASSES == 3 ? 4 : 2) * 2048];
    uint32_t* Ah = smh;
    uint32_t* Bh = smh + 2048;
    uint32_t* Al = (PASSES == 3) ? smh + 4096 : smh;
    uint32_t* Bl = (PASSES == 3) ? smh + 6144 : smh;

    const int tid = threadIdx.x;
    const int lane = tid & 31, wid = tid >> 5;
    const int g = lane >> 2, tig = lane & 3;
    const int wm = wid & 1, wn = wid >> 1;
    const int z = blockIdx.z;
    A  += (size_t)z * sA;
    B1 += (size_t)z * sB;
    B2 += (size_t)z * sB;
    C  += (size_t)z * sC;
    const int m0 = blockIdx.y * 128, n0 = blockIdx.x * 128;

    float acc[16][4];
#pragma unroll
    for (int i = 0; i < 16; i++)
#pragma unroll
        for (int j = 0; j < 4; j++) acc[i][j] = 0.f;

    float4 pA[4], pB[4];
    const int NT = K / 32;

    auto loadA = [&](int kt) {
        const float* Ab = A + (size_t)m0 * lda + kt * 32;
#pragma unroll
        for (int it = 0; it < 4; it++) {
            int task = tid + it * 256;
            int r = task >> 3, cq = task & 7;
            pA[it] = *(const float4*)(Ab + (size_t)r * lda + cq * 4);
        }
    };
    auto loadB = [&](int kt) {
        if (!TRANSB) {
            const float* Bb = B1 + (size_t)n0 * ldb + kt * 32;
#pragma unroll
            for (int it = 0; it < 4; it++) {
                int task = tid + it * 256;
                int r = task >> 3, cq = task & 7;
                pB[it] = *(const float4*)(Bb + (size_t)r * ldb + cq * 4);
            }
        } else {
#pragma unroll
            for (int it = 0; it < 4; it++) {
                int task = tid + it * 256;
                int n = task & 127, q = task >> 7;
                int kb = kt * 32 + q * 4;
                float vv[4];
#pragma unroll
                for (int i = 0; i < 4; i++) {
                    int kk = kb + i;
                    const float* row = (kk < splitK)
                        ? (B1 + (size_t)kk * ldb)
                        : (B2 + (size_t)(kk - splitK) * ldb);
                    vv[i] = row[n0 + n];
                }
                pB[it] = make_float4(vv[0], vv[1], vv[2], vv[3]);
            }
        }
    };
    auto stsAll = [&]() {
#pragma unroll
        for (int it = 0; it < 4; it++) {
            int task = tid + it * 256;
            {
                int r = task >> 3, cq = task & 7;
                float4 v = pA[it];
                v.x *= ascale; v.y *= ascale; v.z *= ascale; v.w *= ascale;
                uint32_t h0 = packh2(v.x, v.y), h1 = packh2(v.z, v.w);
                int w = (2 * cq) ^ ((r << 1) & 14);
                *(uint2*)&Ah[r * 16 + w] = make_uint2(h0, h1);
                if (PASSES == 3) {
                    float2 f0 = unpackh2f(h0), f1 = unpackh2f(h1);
                    *(uint2*)&Al[r * 16 + w] = make_uint2(
                        packh2(v.x - f0.x, v.y - f0.y),
                        packh2(v.z - f1.x, v.w - f1.y));
                }
            }
            {
                int r, cq;
                if (!TRANSB) { r = task >> 3; cq = task & 7; }
                else         { r = task & 127; cq = task >> 7; }
                float4 v = pB[it];
                uint32_t h0 = packh2(v.x, v.y), h1 = packh2(v.z, v.w);
                int w = (2 * cq) ^ ((r << 1) & 14);
                *(uint2*)&Bh[r * 16 + w] = make_uint2(h0, h1);
                if (PASSES == 3) {
                    float2 f0 = unpackh2f(h0), f1 = unpackh2f(h1);
                    *(uint2*)&Bl[r * 16 + w] = make_uint2(
                        packh2(v.x - f0.x, v.y - f0.y),
                        packh2(v.z - f1.x, v.w - f1.y));
                }
            }
        }
    };

    loadA(0); loadB(0);
    for (int kt = 0; kt < NT; kt++) {
        stsAll();
        __syncthreads();
        if (kt + 1 < NT) { loadA(kt + 1); loadB(kt + 1); }
#pragma unroll
        for (int ks = 0; ks < 2; ks++) {
            const int wb = ks * 8;
            uint32_t ah[4][4], bh[4][2], al[4][4], bl[4][2];
#pragma unroll
            for (int mt = 0; mt < 4; mt++) {
                int r0 = wm * 64 + mt * 16 + g, r1 = r0 + 8;
                ah[mt][0] = Ah[hwidx(r0, wb + tig)];
                ah[mt][1] = Ah[hwidx(r1, wb + tig)];
                ah[mt][2] = Ah[hwidx(r0, wb + tig + 4)];
                ah[mt][3] = Ah[hwidx(r1, wb + tig + 4)];
                if (PASSES == 3) {
                    al[mt][0] = Al[hwidx(r0, wb + tig)];
                    al[mt][1] = Al[hwidx(r1, wb + tig)];
                    al[mt][2] = Al[hwidx(r0, wb + tig + 4)];
                    al[mt][3] = Al[hwidx(r1, wb + tig + 4)];
                }
            }
#pragma unroll
            for (int nt = 0; nt < 4; nt++) {
                int rn = wn * 32 + nt * 8 + g;
                bh[nt][0] = Bh[hwidx(rn, wb + tig)];
                bh[nt][1] = Bh[hwidx(rn, wb + tig + 4)];
                if (PASSES == 3) {
                    bl[nt][0] = Bl[hwidx(rn, wb + tig)];
                    bl[nt][1] = Bl[hwidx(rn, wb + tig + 4)];
                }
            }
#pragma unroll
            for (int mt = 0; mt < 4; mt++)
#pragma unroll
                for (int nt = 0; nt < 4; nt++) {
                    mma16816(acc[mt * 4 + nt], ah[mt], bh[nt]);
                    if (PASSES == 3) {
                        mma16816(acc[mt * 4 + nt], ah[mt], bl[nt]);
                        mma16816(acc[mt * 4 + nt], al[mt], bh[nt]);
                    }
                }
        }
        __syncthreads();
    }

    if (!REDUCE) {
#pragma unroll
        for (int mt = 0; mt < 4; mt++) {
            int r0 = m0 + wm * 64 + mt * 16 + g;
            float b0 = bias ? bias[r0] : 0.f;
            float b1 = bias ? bias[r0 + 8] : 0.f;
#pragma unroll
            for (int nt = 0; nt < 4; nt++) {
                int cc = n0 + wn * 32 + nt * 8 + 2 * tig;
                float* c = acc[mt * 4 + nt];
                *(float2*)(C + (size_t)r0 * ldc + cc) =
                    make_float2(c[0] * inv_ascale + b0, c[1] * inv_ascale + b0);
                *(float2*)(C + (size_t)(r0 + 8) * ldc + cc) =
                    make_float2(c[2] * inv_ascale + b1, c[3] * inv_ascale + b1);
            }
        }
    } else {
        float* smax = (float*)smh;
        float* ssum = smax + 512;
#pragma unroll
        for (int mt = 0; mt < 4; mt++) {
            float m0v = -3.0e38f, s0v = 0.f;
            float m1v = -3.0e38f, s1v = 0.f;
#pragma unroll
            for (int nt = 0; nt < 4; nt++) {
                int cc = n0 + wn * 32 + nt * 8 + 2 * tig;
                float* c = acc[mt * 4 + nt];
#pragma unroll
                for (int e = 0; e < 2; e++) {
                    if (cc + e < U_) {
                        float v0 = c[0 + e] * inv_ascale;
                        float v1 = c[2 + e] * inv_ascale;
                        m0v = fmaxf(m0v, v0); s0v += v0;
                        m1v = fmaxf(m1v, v1); s1v += v1;
                    }
                }
            }
#pragma unroll
            for (int off = 1; off <= 2; off <<= 1) {
                m0v = fmaxf(m0v, __shfl_xor_sync(0xffffffffu, m0v, off));
                s0v += __shfl_xor_sync(0xffffffffu, s0v, off);
                m1v = fmaxf(m1v, __shfl_xor_sync(0xffffffffu, m1v, off));
                s1v += __shfl_xor_sync(0xffffffffu, s1v, off);
            }
            if (tig == 0) {
                int r0 = wm * 64 + mt * 16 + g;
                smax[r0 * 4 + wn] = m0v;       ssum[r0 * 4 + wn] = s0v;
                smax[(r0 + 8) * 4 + wn] = m1v; ssum[(r0 + 8) * 4 + wn] = s1v;
            }
        }
        __syncthreads();
        if (tid < 128) {
            float mx = smax[tid * 4];
            float sm = ssum[tid * 4];
#pragma unroll
            for (int w = 1; w < 4; w++) {
                mx = fmaxf(mx, smax[tid * 4 + w]);
                sm += ssum[tid * 4 + w];
            }
            mpart[((size_t)z * L_ + m0 + tid) * 4 + blockIdx.x] = make_float2(mx, sm);
        }
    }
}

// =================================================================================
// gemm_h64: 1-pass fp32-input GEMM, 128x64 tile, 2 CTAs/SM (scores, upd).
// =================================================================================
template <bool TRANSB>
__global__ void __launch_bounds__(256, 2) gemm_h64(
    const float* __restrict__ A, ull sA, int lda,
    const float* __restrict__ B1, ull sB, int ldb,
    float* __restrict__ C, ull sC, int ldc, int K)
{
    __shared__ __align__(16) uint32_t smh[2048 + 1024];
    uint32_t* Ah = smh;
    uint32_t* Bh = smh + 2048;

    const int tid = threadIdx.x;
    const int lane = tid & 31, wid = tid >> 5;
    const int g = lane >> 2, tig = lane & 3;
    const int wm = wid & 1, wn = wid >> 1;
    const int z = blockIdx.z;
    A  += (size_t)z * sA;
    B1 += (size_t)z * sB;
    C  += (size_t)z * sC;
    const int m0 = blockIdx.y * 128, n0 = blockIdx.x * 64;

    float acc[8][4];
#pragma unroll
    for (int i = 0; i < 8; i++)
#pragma unroll
        for (int j = 0; j < 4; j++) acc[i][j] = 0.f;

    float4 pA[4], pB[2];
    const int NT = K / 32;

    auto loadA = [&](int kt) {
        const float* Ab = A + (size_t)m0 * lda + kt * 32;
#pragma unroll
        for (int it = 0; it < 4; it++) {
            int task = tid + it * 256;
            int r = task >> 3, cq = task & 7;
            pA[it] = *(const float4*)(Ab + (size_t)r * lda + cq * 4);
        }
    };
    auto loadB = [&](int kt) {
        if (!TRANSB) {
            const float* Bb = B1 + (size_t)n0 * ldb + kt * 32;
#pragma unroll
            for (int it = 0; it < 2; it++) {
                int task = tid + it * 256;
                int r = task >> 3, cq = task & 7;
                pB[it] = *(const float4*)(Bb + (size_t)r * ldb + cq * 4);
            }
        } else {
#pragma unroll
            for (int it = 0; it < 2; it++) {
                int task = tid + it * 256;
                int n = task & 63, q = task >> 6;
                int kb = kt * 32 + q * 4;
                float vv[4];
#pragma unroll
                for (int i = 0; i < 4; i++)
                    vv[i] = B1[(size_t)(kb + i) * ldb + n0 + n];
                pB[it] = make_float4(vv[0], vv[1], vv[2], vv[3]);
            }
        }
    };
    auto stsAll = [&]() {
#pragma unroll
        for (int it = 0; it < 4; it++) {
            int task = tid + it * 256;
            int r = task >> 3, cq = task & 7;
            float4 v = pA[it];
            int w = (2 * cq) ^ ((r << 1) & 14);
            *(uint2*)&Ah[r * 16 + w] = make_uint2(packh2(v.x, v.y), packh2(v.z, v.w));
        }
#pragma unroll
        for (int it = 0; it < 2; it++) {
            int task = tid + it * 256;
            int r, cq;
            if (!TRANSB) { r = task >> 3; cq = task & 7; }
            else         { r = task & 63; cq = task >> 6; }
            float4 v = pB[it];
            int w = (2 * cq) ^ ((r << 1) & 14);
            *(uint2*)&Bh[r * 16 + w] = make_uint2(packh2(v.x, v.y), packh2(v.z, v.w));
        }
    };

    loadA(0); loadB(0);
    for (int kt = 0; kt < NT; kt++) {
        stsAll();
        __syncthreads();
        if (kt + 1 < NT) { loadA(kt + 1); loadB(kt + 1); }
#pragma unroll
        for (int ks = 0; ks < 2; ks++) {
            const int wb = ks * 8;
            uint32_t ah[4][4], bh[2][2];
#pragma unroll
            for (int mt = 0; mt < 4; mt++) {
                int r0 = wm * 64 + mt * 16 + g, r1 = r0 + 8;
                ah[mt][0] = Ah[hwidx(r0, wb + tig)];
                ah[mt][1] = Ah[hwidx(r1, wb + tig)];
                ah[mt][2] = Ah[hwidx(r0, wb + tig + 4)];
                ah[mt][3] = Ah[hwidx(r1, wb + tig + 4)];
            }
#pragma unroll
            for (int nt = 0; nt < 2; nt++) {
                int rn = wn * 16 + nt * 8 + g;
                bh[nt][0] = Bh[hwidx(rn, wb + tig)];
                bh[nt][1] = Bh[hwidx(rn, wb + tig + 4)];
            }
#pragma unroll
            for (int mt = 0; mt < 4; mt++)
#pragma unroll
                for (int nt = 0; nt < 2; nt++)
                    mma16816(acc[mt * 2 + nt], ah[mt], bh[nt]);
        }
        __syncthreads();
    }

#pragma unroll
    for (int mt = 0; mt < 4; mt++) {
        int r0 = m0 + wm * 64 + mt * 16 + g;
#pragma unroll
        for (int nt = 0; nt < 2; nt++) {
            int cc = n0 + wn * 16 + nt * 8 + 2 * tig;
            float* c = acc[mt * 2 + nt];
            *(float2*)(C + (size_t)r0 * ldc + cc) = make_float2(c[0], c[1]);
            *(float2*)(C + (size_t)(r0 + 8) * ldc + cc) = make_float2(c[2], c[3]);
        }
    }
}

// ---------------- small kernels --------------------------------------------------
__global__ void topk_kernel()
{
    __shared__ unsigned long long key[4096];
    int b = blockIdx.x;
    for (int i = threadIdx.x; i < 4096; i += 1024) {
        const float2* p = &g_mpart[((size_t)b * L_ + i) * 4];
        float mx = p[0].x, sm = p[0].y;
#pragma unroll
        for (int w = 1; w < 4; w++) { mx = fmaxf(mx, p[w].x); sm += p[w].y; }
        float M = mx - sm * (1.0f / 4096.0f);
        unsigned u = __float_as_uint(M);
        u = (u & 0x80000000u) ? ~u : (u | 0x80000000u);
        key[i] = ((unsigned long long)u << 32) | (unsigned)(4095 - i);
    }
    __syncthreads();
    for (int k = 2; k <= 4096; k <<= 1) {
        for (int j = k >> 1; j > 0; j >>= 1) {
            for (int i = threadIdx.x; i < 4096; i += 1024) {
                int ixj = i ^ j;
                if (ixj > i) {
                    bool up = ((i & k) == 0);
                    unsigned long long a = key[i], c = key[ixj];
                    if ((a > c) == up) { key[i] = c; key[ixj] = a; }
                }
            }
            __syncthreads();
        }
    }
    for (int t = threadIdx.x; t < U_; t += 1024) {
        unsigned long long kk = key[4095 - t];
        g_top[b * U_ + t] = 4095 - (int)(unsigned)(kk & 0xFFFFFFFFu);
    }
}

__global__ void gather_qsel()
{
    int b = blockIdx.y, u = blockIdx.x;
    int r = g_top[b * U_ + u];
    const float4* s = (const float4*)(g_q + ((size_t)b * L_ + r) * D_);
    float4*       d = (float4*)(g_qsel + ((size_t)b * UP_ + u) * D_);
    d[threadIdx.x] = s[threadIdx.x];
}

__global__ void softmax_kernel()
{
    int b = blockIdx.y, u = blockIdx.x;
    float* row = g_attn + ((size_t)b * UP_ + (size_t)u) * L_;
    int tid = threadIdx.x;
    int lane = tid & 31, wid = tid >> 5;

    float v[16]; float mx = -3.0e38f;
#pragma unroll
    for (int i = 0; i < 16; i++) {
        float t = row[tid + i * 256] * SCALE_;
        v[i] = t; mx = fmaxf(mx, t);
    }
    __shared__ float red[8];
    __shared__ float bcast;
#pragma unroll
    for (int o = 16; o; o >>= 1) mx = fmaxf(mx, __shfl_xor_sync(0xffffffffu, mx, o));
    if (!lane) red[wid] = mx;
    __syncthreads();
    if (!tid) { float m2 = red[0]; for (int w = 1; w < 8; w++) m2 = fmaxf(m2, red[w]); bcast = m2; }
    __syncthreads();
    mx = bcast;

    float sm = 0.f;
#pragma unroll
    for (int i = 0; i < 16; i++) { v[i] = expf(v[i] - mx); sm += v[i]; }
#pragma unroll
    for (int o = 16; o; o >>= 1) sm += __shfl_xor_sync(0xffffffffu, sm, o);
    __syncthreads();
    if (!lane) red[wid] = sm;
    __syncthreads();
    if (!tid) { float s = red[0]; for (int w = 1; w < 8; w++) s += red[w]; bcast = 1.0f / s; }
    __syncthreads();
    float inv = bcast;
#pragma unroll
    for (int i = 0; i < 16; i++) row[tid + i * 256] = v[i] * inv;
}

__global__ void vmean_part()
{
    int b = blockIdx.y, ch = blockIdx.x;
    int d = threadIdx.x;
    const float* base = g_v + (size_t)b * L_ * D_ + (size_t)ch * 512 * D_ + d;
    float s = 0.f;
    for (int l = 0; l < 512; l++) s += base[(size_t)l * D_];
    g_part[(b * 8 + ch) * D_ + d] = s;
}

__global__ void fill_kernel(float* __restrict__ out)
{
    int b = blockIdx.y;
    int l0 = blockIdx.x * 8;
    int d = threadIdx.x;
    float s = 0.f;
#pragma unroll
    for (int c = 0; c < 8; c++) s += g_part[(b * 8 + c) * D_ + d];
    s *= (1.0f / 4096.0f);
    float* o = out + (size_t)b * L_ * D_ + (size_t)l0 * D_ + d;
#pragma unroll
    for (int r = 0; r < 8; r++) o[(size_t)r * D_] = s;
}

__global__ void scatter_kernel(float* __restrict__ out)
{
    int b = blockIdx.y, u = blockIdx.x;
    int r = g_top[b * U_ + u];
    const float4* s = (const float4*)(g_upd + ((size_t)b * UP_ + u) * D_);
    float4*       d = (float4*)(out + ((size_t)b * L_ + r) * D_);
    d[threadIdx.x] = s[threadIdx.x];
}

// =================================================================================
extern "C" void kernel_launch(void* const* d_in, const int* in_sizes, int n_in,
                              void* d_out, int out_size)
{
    const float* in1 = (const float*)d_in[0];
    const float* in2 = (const float*)d_in[1];
    const float* Wq  = (const float*)d_in[2];
    const float* bq  = (const float*)d_in[3];
    const float* Wk  = (const float*)d_in[4];
    const float* bk  = (const float*)d_in[5];
    const float* Wv  = (const float*)d_in[6];
    const float* bv  = (const float*)d_in[7];
    const int*   idx = (const int*)d_in[8];
    float* out = (float*)d_out;

    __half *xhp, *xlp;
    float *qp, *kp, *vp, *attnp, *ksp, *qsp, *upp;
    float2* mpp;
    cudaGetSymbolAddress((void**)&xhp,  g_xh);
    cudaGetSymbolAddress((void**)&xlp,  g_xl);
    cudaGetSymbolAddress((void**)&qp,   g_q);
    cudaGetSymbolAddress((void**)&kp,   g_k);
    cudaGetSymbolAddress((void**)&vp,   g_v);
    cudaGetSymbolAddress((void**)&attnp,g_attn);
    cudaGetSymbolAddress((void**)&ksp,  g_ksamp);
    cudaGetSymbolAddress((void**)&qsp,  g_qsel);
    cudaGetSymbolAddress((void**)&upp,  g_upd);
    cudaGetSymbolAddress((void**)&mpp,  g_mpart);

    const ull sXT  = (ull)L_ * D_;
    const ull sQKV = (ull)L_ * D_;
    const float AS = 1024.f, IAS = 1.f / 1024.f;

    // 0. transpose + pre-split X
    split_x<<<dim3(64, 8, B_), 256>>>(in1, in2);

    // 1. projections: q 3-pass (selection-critical everywhere);
    //    k 1-pass (only scores consumes full k); v 1-pass.
    gemm_hx<3><<<dim3(32, 4, B_), 256>>>(
        Wq, 512, xhp, xlp, sXT, qp, sQKV, 4096, bq, 512, AS, IAS);
    gemm_hx<1><<<dim3(32, 4, B_), 256>>>(
        Wk, 512, xhp, xhp, sXT, kp, sQKV, 4096, bk, 512, AS, IAS);
    gemm_hx<1><<<dim3(32, 4, B_), 256>>>(
        Wv, 512, xhp, xhp, sXT, vp, sQKV, 4096, bv, 512, AS, IAS);

    // 2. ksamp: 450 sampled k rows at full 3-pass precision (bit-identical
    //    to the old full 3-pass proj-k + gather path)
    ksamp_proj<<<dim3(4, 8, B_), 256>>>(Wk, bk, idx);

    // 3. QKs = q @ ksamp^T, fused {max,sum} reduction
    gemm_h<false, 3, true><<<dim3(4, 32, B_), 256>>>(
        qp, sQKV, 512, ksp, ksp, (ull)UP_ * D_, 512, 512,
        nullptr, 0ull, 0, nullptr, 512, AS, IAS, mpp);

    // 4-5. top-450 (M inline), Q_sel gather
    topk_kernel<<<B_, 1024>>>();
    gather_qsel<<<dim3(U_, B_), 128>>>();

    // 6. scores = Q_sel @ K^T : 1-pass 128x64 @ 2 CTA/SM
    gemm_h64<false><<<dim3(64, 4, B_), 256>>>(
        qsp, (ull)UP_ * D_, 512, kp, sQKV, 512,
        attnp, (ull)UP_ * L_, 4096, 512);

    // 7. softmax
    softmax_kernel<<<dim3(U_, B_), 256>>>();

    // 8. upd = attn @ V : 1-pass 128x64 @ 2 CTA/SM, V is (K x N) -> TRANSB
    gemm_h64<true><<<dim3(8, 4, B_), 256>>>(
        attnp, (ull)UP_ * L_, 4096, vp, sQKV, 512,
        upp, (ull)UP_ * D_, 512, 4096);

    // 9. mean fill + scatter
    vmean_part<<<dim3(8, B_), 512>>>();
    fill_kernel<<<dim3(512, B_), 512>>>(out);
    scatter_kernel<<<dim3(U_, B_), 128>>>(out);
}